// round 13
// baseline (speedup 1.0000x reference)
#include <cuda_runtime.h>
#include <cstdint>

#define BATCH 256
#define SEQ   197
#define SN    196
#define DIM   768
#define GRID  14
#define MQK   (BATCH*SEQ)
#define MH    (BATCH*SN)
#define MV    (BATCH*64)
#define H60   60
#define K2    1536

__device__ float g_q [(size_t)MQK * DIM];
__device__ float g_k [(size_t)MQK * DIM];
__device__ float g_vs[(size_t)MV  * DIM];
__device__ float g_h1[(size_t)MH  * H60];
__device__ float g_sample[(size_t)MH * 2];
__device__ float g_coords[(size_t)MH * 2];
__device__ float g_x32 [(size_t)MQK * DIM];
__device__ float g_wq32[(size_t)DIM * DIM];
__device__ float g_wk32[(size_t)DIM * DIM];
__device__ float g_wv32[(size_t)DIM * DIM];
__device__ float g_w132[(size_t)H60 * K2];

__device__ __forceinline__ uint32_t f2tf32(float f) {
    uint32_t u;
    asm("cvt.rna.tf32.f32 %0, %1;" : "=r"(u) : "f"(f));
    return u;
}
__device__ __forceinline__ float tf32r(float f) { return __uint_as_float(f2tf32(f)); }

__device__ __forceinline__ void mma_tf32(float (&d)[4], const uint32_t (&a)[4], const uint32_t (&b)[2]) {
    asm volatile(
        "mma.sync.aligned.m16n8k8.row.col.f32.tf32.tf32.f32 "
        "{%0,%1,%2,%3}, {%4,%5,%6,%7}, {%8,%9}, {%0,%1,%2,%3};\n"
        : "+f"(d[0]), "+f"(d[1]), "+f"(d[2]), "+f"(d[3])
        : "r"(a[0]), "r"(a[1]), "r"(a[2]), "r"(a[3]), "r"(b[0]), "r"(b[1]));
}

__device__ __forceinline__ void ldsm_x4(uint32_t& r0, uint32_t& r1, uint32_t& r2, uint32_t& r3, uint32_t addr) {
    asm volatile("ldmatrix.sync.aligned.m8n8.x4.shared.b16 {%0,%1,%2,%3}, [%4];"
                 : "=r"(r0), "=r"(r1), "=r"(r2), "=r"(r3) : "r"(addr));
}

__device__ __forceinline__ void cp16(uint32_t dst, const float* src) {
    asm volatile("cp.async.cg.shared.global [%0], [%1], 16;" :: "r"(dst), "l"(src) : "memory");
}
#define CP_COMMIT() asm volatile("cp.async.commit_group;" ::: "memory")
#define CP_WAIT1()  asm volatile("cp.async.wait_group 1;" ::: "memory")
#define CP_WAIT0()  asm volatile("cp.async.wait_group 0;" ::: "memory")

// ---- one-time tf32 rounding pass: X, Wq, Wk, Wv, W1 ----
__global__ __launch_bounds__(256) void k_cvt(const float4* __restrict__ x,
    const float4* __restrict__ Wq, const float4* __restrict__ Wk,
    const float4* __restrict__ Wv, const float4* __restrict__ W1)
{
    const int i = blockIdx.x * 256 + threadIdx.x;   // 39642*256 exact
    float4 v; float4* dst;
    if (i < 9682944)       { v = x[i];             dst = reinterpret_cast<float4*>(g_x32) + i; }
    else if (i < 9830400)  { v = Wq[i - 9682944];  dst = reinterpret_cast<float4*>(g_wq32) + (i - 9682944); }
    else if (i < 9977856)  { v = Wk[i - 9830400];  dst = reinterpret_cast<float4*>(g_wk32) + (i - 9830400); }
    else if (i < 10125312) { v = Wv[i - 9977856];  dst = reinterpret_cast<float4*>(g_wv32) + (i - 9977856); }
    else                   { v = W1[i - 10125312]; dst = reinterpret_cast<float4*>(g_w132) + (i - 10125312); }
    v.x = tf32r(v.x); v.y = tf32r(v.y); v.z = tf32r(v.z); v.w = tf32r(v.w);
    *dst = v;
}

// K-step 16, row stride 20 words. qk/v stage: A 128x20 + B 128x20 = 20480 B.
#define SSTG  20480u
#define BOFF  10240u
// h1 stage: A 128x20 + B 64x20 = 15360 B
#define SSTG_H 15360u

// ============================================================
// TF32 GEMM, 3-stage cp.async, 1 barrier/iter: Y = A@W^T + bias
// Block 128x128, 8 warps 2Mx4N (warp 64x32). 48 K-iters of 16.
// grid: rowTile*12 + (z*6 + colTile); col/z fastest for L2 reuse.
// ============================================================
__global__ __launch_bounds__(256, 3) void k_gemm_qk_t(
    const float* __restrict__ bq, const float* __restrict__ bk)
{
    extern __shared__ __align__(16) uint32_t dsm[];

    const int bx  = blockIdx.x;
    const int rt  = bx / 12;
    const int rem = bx - rt * 12;
    const int ct  = rem % 6;
    const int zz  = rem / 6;

    const float* W    = zz ? g_wk32 : g_wq32;
    const float* bias = zz ? bk : bq;
    float*       Y    = zz ? g_k : g_q;

    const int tid  = threadIdx.x;
    const int lane = tid & 31;
    const int wid  = tid >> 5;
    const int warpM = wid & 1;
    const int warpN = wid >> 1;

    const int row0 = rt * 128;
    const int col0 = ct * 128;

    // loader: tid<128 -> A row tid; else B row tid-128. 4 cp16 (64B) each.
    const float* mysrc = (tid < 128)
        ? (g_x32 + (size_t)(row0 + tid) * DIM)
        : (W + (size_t)(col0 + tid - 128) * DIM);
    const uint32_t sm0 = (uint32_t)__cvta_generic_to_shared(dsm);
    const uint32_t myoff = (tid < 128) ? ((uint32_t)tid * 80u)
                                       : (BOFF + (uint32_t)(tid - 128) * 80u);

    const uint32_t a_b0 = sm0 + (((warpM*64 + (lane & 15)) * 20 + ((lane >> 4) << 2)) << 2);
    const uint32_t b_b0 = sm0 + BOFF + (((warpN*32 + (lane & 15)) * 20 + ((lane >> 4) << 2)) << 2);

    float acc[4][4][4];
    #pragma unroll
    for (int mt = 0; mt < 4; mt++)
        #pragma unroll
        for (int nt = 0; nt < 4; nt++)
            #pragma unroll
            for (int i = 0; i < 4; i++) acc[mt][nt][i] = 0.f;

    // preload stages 0,1
    #pragma unroll
    for (int st = 0; st < 2; st++) {
        const uint32_t d = sm0 + st * SSTG + myoff;
        const float* s = mysrc + st * 16;
        #pragma unroll
        for (int i = 0; i < 4; i++) cp16(d + i * 16u, s + i * 4);
        CP_COMMIT();
    }

    uint32_t stg = 0;   // byte offset of stage (i%3)
    for (int it = 0; it < 48; it++) {
        if (it < 47) CP_WAIT1(); else CP_WAIT0();
        __syncthreads();
        if (it + 2 < 48) {
            const uint32_t d = sm0 + (uint32_t)((it + 2) % 3) * SSTG + myoff;
            const float* s = mysrc + (it + 2) * 16;
            #pragma unroll
            for (int i = 0; i < 4; i++) cp16(d + i * 16u, s + i * 4);
            CP_COMMIT();
        }
        const uint32_t ab = a_b0 + stg;
        const uint32_t bb = b_b0 + stg;
        #pragma unroll
        for (int ks = 0; ks < 2; ks++) {
            uint32_t af[4][4], bf[4][2];
            #pragma unroll
            for (int mt = 0; mt < 4; mt++)
                ldsm_x4(af[mt][0], af[mt][1], af[mt][2], af[mt][3],
                        ab + ((mt*16*20 + ks*8) << 2));
            #pragma unroll
            for (int nt2 = 0; nt2 < 2; nt2++) {
                uint32_t r0, r1, r2, r3;
                ldsm_x4(r0, r1, r2, r3, bb + ((nt2*16*20 + ks*8) << 2));
                bf[2*nt2  ][0] = r0; bf[2*nt2+1][0] = r1;
                bf[2*nt2  ][1] = r2; bf[2*nt2+1][1] = r3;
            }
            #pragma unroll
            for (int mt = 0; mt < 4; mt++)
                #pragma unroll
                for (int nt = 0; nt < 4; nt++)
                    mma_tf32(acc[mt][nt], af[mt], bf[nt]);
        }
        stg += SSTG; if (stg == 3 * SSTG) stg = 0;
    }

    #pragma unroll
    for (int nt = 0; nt < 4; nt++) {
        const int c = col0 + warpN*32 + nt*8 + 2*(lane & 3);
        const float b0v = bias[c];
        const float b1v = bias[c + 1];
        #pragma unroll
        for (int mt = 0; mt < 4; mt++) {
            const int r = row0 + warpM*64 + mt*16 + (lane >> 2);
            float2 o0 = make_float2(tf32r(acc[mt][nt][0] + b0v), tf32r(acc[mt][nt][1] + b1v));
            float2 o1 = make_float2(tf32r(acc[mt][nt][2] + b0v), tf32r(acc[mt][nt][3] + b1v));
            *reinterpret_cast<float2*>(Y + (size_t)r * DIM + c)       = o0;
            *reinterpret_cast<float2*>(Y + (size_t)(r + 8) * DIM + c) = o1;
        }
    }
}

// ============================================================
// TF32 V projection (64 reachable tokens/batch), same pipeline.
// ============================================================
__global__ __launch_bounds__(256, 3) void k_gemm_v_t(const float* __restrict__ bv)
{
    extern __shared__ __align__(16) uint32_t dsm[];

    const int bx = blockIdx.x;
    const int rt = bx / 6;
    const int ct = bx - rt * 6;

    const int tid  = threadIdx.x;
    const int lane = tid & 31;
    const int wid  = tid >> 5;
    const int warpM = wid & 1;
    const int warpN = wid >> 1;

    const int row0 = rt * 128;
    const int col0 = ct * 128;

    const float* mysrc;
    if (tid < 128) {
        const int r_g = row0 + tid;
        const int bb_ = r_g >> 6, jj = r_g & 63;
        const int token = 1 + (6 + (jj >> 3)) * GRID + (6 + (jj & 7));
        mysrc = g_x32 + (size_t)(bb_ * SEQ + token) * DIM;
    } else {
        mysrc = g_wv32 + (size_t)(col0 + tid - 128) * DIM;
    }
    const uint32_t sm0 = (uint32_t)__cvta_generic_to_shared(dsm);
    const uint32_t myoff = (tid < 128) ? ((uint32_t)tid * 80u)
                                       : (BOFF + (uint32_t)(tid - 128) * 80u);

    const uint32_t a_b0 = sm0 + (((warpM*64 + (lane & 15)) * 20 + ((lane >> 4) << 2)) << 2);
    const uint32_t b_b0 = sm0 + BOFF + (((warpN*32 + (lane & 15)) * 20 + ((lane >> 4) << 2)) << 2);

    float acc[4][4][4];
    #pragma unroll
    for (int mt = 0; mt < 4; mt++)
        #pragma unroll
        for (int nt = 0; nt < 4; nt++)
            #pragma unroll
            for (int i = 0; i < 4; i++) acc[mt][nt][i] = 0.f;

    #pragma unroll
    for (int st = 0; st < 2; st++) {
        const uint32_t d = sm0 + st * SSTG + myoff;
        const float* s = mysrc + st * 16;
        #pragma unroll
        for (int i = 0; i < 4; i++) cp16(d + i * 16u, s + i * 4);
        CP_COMMIT();
    }

    uint32_t stg = 0;
    for (int it = 0; it < 48; it++) {
        if (it < 47) CP_WAIT1(); else CP_WAIT0();
        __syncthreads();
        if (it + 2 < 48) {
            const uint32_t d = sm0 + (uint32_t)((it + 2) % 3) * SSTG + myoff;
            const float* s = mysrc + (it + 2) * 16;
            #pragma unroll
            for (int i = 0; i < 4; i++) cp16(d + i * 16u, s + i * 4);
            CP_COMMIT();
        }
        const uint32_t ab = a_b0 + stg;
        const uint32_t bb = b_b0 + stg;
        #pragma unroll
        for (int ks = 0; ks < 2; ks++) {
            uint32_t af[4][4], bf[4][2];
            #pragma unroll
            for (int mt = 0; mt < 4; mt++)
                ldsm_x4(af[mt][0], af[mt][1], af[mt][2], af[mt][3],
                        ab + ((mt*16*20 + ks*8) << 2));
            #pragma unroll
            for (int nt2 = 0; nt2 < 2; nt2++) {
                uint32_t r0, r1, r2, r3;
                ldsm_x4(r0, r1, r2, r3, bb + ((nt2*16*20 + ks*8) << 2));
                bf[2*nt2  ][0] = r0; bf[2*nt2+1][0] = r1;
                bf[2*nt2  ][1] = r2; bf[2*nt2+1][1] = r3;
            }
            #pragma unroll
            for (int mt = 0; mt < 4; mt++)
                #pragma unroll
                for (int nt = 0; nt < 4; nt++)
                    mma_tf32(acc[mt][nt], af[mt], bf[nt]);
        }
        stg += SSTG; if (stg == 3 * SSTG) stg = 0;
    }

    #pragma unroll
    for (int nt = 0; nt < 4; nt++) {
        const int c = col0 + warpN*32 + nt*8 + 2*(lane & 3);
        const float b0v = bv[c];
        const float b1v = bv[c + 1];
        #pragma unroll
        for (int mt = 0; mt < 4; mt++) {
            const int r = row0 + warpM*64 + mt*16 + (lane >> 2);
            float2 o0 = make_float2(acc[mt][nt][0] + b0v, acc[mt][nt][1] + b1v);
            float2 o1 = make_float2(acc[mt][nt][2] + b0v, acc[mt][nt][3] + b1v);
            *reinterpret_cast<float2*>(g_vs + (size_t)r * DIM + c)       = o0;
            *reinterpret_cast<float2*>(g_vs + (size_t)(r + 8) * DIM + c) = o1;
        }
    }
}

// ============================================================
// TF32 MLP layer 1: h1 = relu(concat(q,k)@W1^T + b1)
// Block 128x64; 8 warps 4Mx2N. 96 K-iters of 16. 3-stage pipeline.
// ============================================================
__global__ __launch_bounds__(256, 3) void k_gemm_h1_t(const float* __restrict__ b1)
{
    extern __shared__ __align__(16) uint32_t dsm[];

    const int tid  = threadIdx.x;
    const int lane = tid & 31;
    const int wid  = tid >> 5;
    const int warpM = wid & 3;
    const int warpN = wid >> 2;

    const int row0 = blockIdx.x * 128;

    // A loader rows (virtual concat handled per-k0), B loader rows 0..59
    size_t aoff = 0;
    if (tid < 128) {
        const int r_g = row0 + tid;
        const int bb_ = r_g / SN;
        const int tt  = r_g - bb_ * SN;
        aoff = (size_t)(bb_ * SEQ + tt + 1) * DIM;
    }
    const bool isB = (tid >= 128) && (tid < 192) && ((tid - 128) < H60);
    const float* brow = g_w132 + (size_t)(tid - 128) * K2;

    const uint32_t sm0 = (uint32_t)__cvta_generic_to_shared(dsm);
    const uint32_t myoff = (tid < 128) ? ((uint32_t)tid * 80u)
                                       : (BOFF + (uint32_t)(tid - 128) * 80u);

    const uint32_t a_b0 = sm0 + (((warpM*32 + (lane & 15)) * 20 + ((lane >> 4) << 2)) << 2);
    const uint32_t b_b0 = sm0 + BOFF + (((warpN*32 + (lane & 15)) * 20 + ((lane >> 4) << 2)) << 2);

    // zero B rows 60..63 in all 3 stages (16 words each row)
    if (tid < 48) {
        const uint32_t st = (uint32_t)(tid >> 4);
        const int r = 60 + ((tid >> 2) & 3);
        const int i = tid & 3;
        const uint32_t a = sm0 + st * SSTG_H + BOFF + (((uint32_t)r * 20u + (uint32_t)i * 4u) << 2);
        asm volatile("st.shared.v4.b32 [%0], {%1, %1, %1, %1};" :: "r"(a), "r"(0u) : "memory");
    }

    float acc[2][4][4];
    #pragma unroll
    for (int mt = 0; mt < 2; mt++)
        #pragma unroll
        for (int nt = 0; nt < 4; nt++)
            #pragma unroll
            for (int i = 0; i < 4; i++) acc[mt][nt][i] = 0.f;

    // preload stages 0,1
    #pragma unroll
    for (int st = 0; st < 2; st++) {
        const uint32_t d = sm0 + st * SSTG_H + myoff;
        const int k0 = st * 16;
        if (tid < 128) {
            const float* s = g_q + aoff + k0;   // k0 < DIM here
            #pragma unroll
            for (int i = 0; i < 4; i++) cp16(d + i * 16u, s + i * 4);
        } else if (isB) {
            #pragma unroll
            for (int i = 0; i < 4; i++) cp16(d + i * 16u, brow + k0 + i * 4);
        }
        CP_COMMIT();
    }

    uint32_t stg = 0;
    for (int it = 0; it < 96; it++) {
        if (it < 95) CP_WAIT1(); else CP_WAIT0();
        __syncthreads();
        if (it + 2 < 96) {
            const uint32_t d = sm0 + (uint32_t)((it + 2) % 3) * SSTG_H + myoff;
            const int k0 = (it + 2) * 16;
            if (tid < 128) {
                const float* s = (k0 < DIM) ? (g_q + aoff + k0) : (g_k + aoff + k0 - DIM);
                #pragma unroll
                for (int i = 0; i < 4; i++) cp16(d + i * 16u, s + i * 4);
            } else if (isB) {
                #pragma unroll
                for (int i = 0; i < 4; i++) cp16(d + i * 16u, brow + k0 + i * 4);
            }
            CP_COMMIT();
        }
        const uint32_t ab = a_b0 + stg;
        const uint32_t bb = b_b0 + stg;
        #pragma unroll
        for (int ks = 0; ks < 2; ks++) {
            uint32_t af[2][4], bf[4][2];
            #pragma unroll
            for (int mt = 0; mt < 2; mt++)
                ldsm_x4(af[mt][0], af[mt][1], af[mt][2], af[mt][3],
                        ab + ((mt*16*20 + ks*8) << 2));
            #pragma unroll
            for (int nt2 = 0; nt2 < 2; nt2++) {
                uint32_t r0, r1, r2, r3;
                ldsm_x4(r0, r1, r2, r3, bb + ((nt2*16*20 + ks*8) << 2));
                bf[2*nt2  ][0] = r0; bf[2*nt2+1][0] = r1;
                bf[2*nt2  ][1] = r2; bf[2*nt2+1][1] = r3;
            }
            #pragma unroll
            for (int mt = 0; mt < 2; mt++)
                #pragma unroll
                for (int nt = 0; nt < 4; nt++)
                    mma_tf32(acc[mt][nt], af[mt], bf[nt]);
        }
        stg += SSTG_H; if (stg == 3 * SSTG_H) stg = 0;
    }

    #pragma unroll
    for (int nt = 0; nt < 4; nt++) {
        const int c = warpN*32 + nt*8 + 2*(lane & 3);
        const float b0v = (c     < H60) ? b1[c]     : 0.f;
        const float b1v = (c + 1 < H60) ? b1[c + 1] : 0.f;
        #pragma unroll
        for (int mt = 0; mt < 2; mt++) {
            const int r = row0 + warpM*32 + mt*16 + (lane >> 2);
            if (c < H60) {
                g_h1[(size_t)r * H60 + c]       = fmaxf(acc[mt][nt][0] + b0v, 0.f);
                g_h1[(size_t)(r + 8) * H60 + c] = fmaxf(acc[mt][nt][2] + b0v, 0.f);
            }
            if (c + 1 < H60) {
                g_h1[(size_t)r * H60 + c + 1]       = fmaxf(acc[mt][nt][1] + b1v, 0.f);
                g_h1[(size_t)(r + 8) * H60 + c + 1] = fmaxf(acc[mt][nt][3] + b1v, 0.f);
            }
        }
    }
}

// ============================================================
// MLP layers 2+3 (unchanged)
// ============================================================
__global__ __launch_bounds__(256) void k_mlp23(
    const float* __restrict__ W2, const float* __restrict__ b2,
    const float* __restrict__ W3, const float* __restrict__ b3)
{
    __shared__ float W2s[60*61], W3s[120], b2s[60], b3s[2], h1s[16][60], h2s[16][60];
    const int tid = threadIdx.x;
    for (int i = tid; i < 3600; i += 256) { int rr = i / 60, cc = i - rr * 60; W2s[rr*61+cc] = W2[i]; }
    if (tid < 120) W3s[tid] = W3[tid];
    if (tid < 60)  b2s[tid] = b2[tid];
    if (tid < 2)   b3s[tid] = b3[tid];
    const int r0 = blockIdx.x * 16;
    for (int i = tid; i < 960; i += 256) { int t = i / 60, c = i - t * 60; h1s[t][c] = g_h1[(size_t)(r0+t)*H60 + c]; }
    __syncthreads();
    const int tg = tid >> 6, f = tid & 63;
    if (f < H60) {
        float a0 = b2s[f], a1 = a0, a2 = a0, a3 = a0;
        #pragma unroll 4
        for (int g = 0; g < H60; g++) {
            const float w = W2s[f*61 + g];
            a0 = fmaf(w, h1s[tg*4+0][g], a0); a1 = fmaf(w, h1s[tg*4+1][g], a1);
            a2 = fmaf(w, h1s[tg*4+2][g], a2); a3 = fmaf(w, h1s[tg*4+3][g], a3);
        }
        h2s[tg*4+0][f] = fmaxf(a0, 0.f); h2s[tg*4+1][f] = fmaxf(a1, 0.f);
        h2s[tg*4+2][f] = fmaxf(a2, 0.f); h2s[tg*4+3][f] = fmaxf(a3, 0.f);
    }
    __syncthreads();
    if (tid < 32) {
        int t2 = tid >> 1, c = tid & 1;
        float s = b3s[c];
        #pragma unroll 4
        for (int g = 0; g < H60; g++) s = fmaf(W3s[c*60+g], h2s[t2][g], s);
        g_sample[(size_t)(r0+t2)*2 + c] = 1.f / (1.f + expf(-s));
    }
}

__global__ void k_coords()
{
    const int id = blockIdx.x * 256 + threadIdx.x;
    const int b = id / SN, p = id - b * SN;
    const int q1 = 2 * p, q2 = 2 * p + 1;
    float gx = (q1 < SN) ? g_sample[(size_t)(b*SN+q1)*2+0] : g_sample[(size_t)(b*SN+q1-SN)*2+1];
    float gy = (q2 < SN) ? g_sample[(size_t)(b*SN+q2)*2+0] : g_sample[(size_t)(b*SN+q2-SN)*2+1];
    g_coords[(size_t)id*2+0] = ((gx + 1.f) * (float)GRID - 1.f) * 0.5f;
    g_coords[(size_t)id*2+1] = ((gy + 1.f) * (float)GRID - 1.f) * 0.5f;
}

__global__ __launch_bounds__(256) void k_epilogue(float* __restrict__ out)
{
    const int bs = blockIdx.x, b = bs / SEQ, s = bs - b * SEQ;
    const int tid = threadIdx.x, lane = tid & 31, wid = tid >> 5;
    __shared__ float red[8];
    __shared__ float sigsh;
    const size_t qbase = (size_t)bs * DIM;
    float w[4]; size_t rowk[4], rowv[4]; bool vk[4], vv[4];

    if (s > 0) {
        const int p = s - 1;
        const float ix = g_coords[(size_t)(b*SN+p)*2+0];
        const float iy = g_coords[(size_t)(b*SN+p)*2+1];
        const float ix0f = floorf(ix), iy0f = floorf(iy);
        const float wx1 = ix - ix0f, wx0 = 1.f - wx1;
        const float wy1 = iy - iy0f, wy0 = 1.f - wy1;
        const int x0 = (int)ix0f, y0 = (int)iy0f;
        const int xs[4] = {x0, x0+1, x0, x0+1};
        const int ys[4] = {y0, y0, y0+1, y0+1};
        const float ws[4] = {wy0*wx0, wy0*wx1, wy1*wx0, wy1*wx1};
        #pragma unroll
        for (int c = 0; c < 4; c++) {
            const int x = xs[c], y = ys[c];
            const bool v = (x >= 0) && (x <= GRID-1) && (y >= 0) && (y <= GRID-1);
            vk[c] = v; w[c] = ws[c];
            rowk[c] = v ? (size_t)(b * SEQ + 1 + y * GRID + x) * DIM : 0;
            const bool v2 = v && (x >= 6) && (y >= 6);
            vv[c] = v2;
            rowv[c] = v2 ? (size_t)(b * 64 + (y-6)*8 + (x-6)) * DIM : 0;
        }
    }

    float part = 0.f, svreg[3];
    #pragma unroll
    for (int it = 0; it < 3; it++) {
        const int d = tid + it * 256;
        float skd, svd;
        if (s == 0) { skd = 1.f; svd = 1.f; }
        else {
            skd = 0.f; svd = 0.f;
            #pragma unroll
            for (int c = 0; c < 4; c++) {
                if (vk[c]) skd = fmaf(w[c], g_k[rowk[c] + d], skd);
                if (vv[c]) svd = fmaf(w[c], g_vs[rowv[c] + d], svd);
            }
        }
        svreg[it] = svd;
        part = fmaf(skd, g_q[qbase + d], part);
    }
    #pragma unroll
    for (int off = 16; off > 0; off >>= 1) part += __shfl_xor_sync(0xffffffffu, part, off);
    if (lane == 0) red[wid] = part;
    __syncthreads();
    if (tid == 0) {
        float sum = 0.f;
        #pragma unroll
        for (int i = 0; i < 8; i++) sum += red[i];
        sigsh = 1.f / (1.f + expf(-0.01f * sum));
    }
    __syncthreads();
    const float sg = sigsh;
    #pragma unroll
    for (int it = 0; it < 3; it++) out[qbase + tid + it*256] = sg * svreg[it];
}

extern "C" void kernel_launch(void* const* d_in, const int* in_sizes, int n_in,
                              void* d_out, int out_size)
{
    const float* x  = (const float*)d_in[0];
    const float* Wq = (const float*)d_in[2];  const float* bq = (const float*)d_in[3];
    const float* Wk = (const float*)d_in[4];  const float* bk = (const float*)d_in[5];
    const float* Wv = (const float*)d_in[6];  const float* bv = (const float*)d_in[7];
    const float* W1 = (const float*)d_in[8];  const float* b1 = (const float*)d_in[9];
    const float* W2 = (const float*)d_in[10]; const float* b2 = (const float*)d_in[11];
    const float* W3 = (const float*)d_in[12]; const float* b3 = (const float*)d_in[13];
    float* out = (float*)d_out;

    static bool attr_done = false;
    if (!attr_done) {
        cudaFuncSetAttribute(k_gemm_qk_t, cudaFuncAttributeMaxDynamicSharedMemorySize, 3 * SSTG);
        cudaFuncSetAttribute(k_gemm_v_t,  cudaFuncAttributeMaxDynamicSharedMemorySize, 3 * SSTG);
        cudaFuncSetAttribute(k_gemm_h1_t, cudaFuncAttributeMaxDynamicSharedMemorySize, 3 * SSTG_H);
        attr_done = true;
    }

    k_cvt<<<39642, 256>>>((const float4*)x, (const float4*)Wq, (const float4*)Wk,
                          (const float4*)Wv, (const float4*)W1);
    k_gemm_qk_t<<<394 * 12, 256, 3 * SSTG>>>(bq, bk);
    k_gemm_v_t<<<128 * 6, 256, 3 * SSTG>>>(bv);
    k_gemm_h1_t<<<392, 256, 3 * SSTG_H>>>(b1);
    k_mlp23<<<3136, 256>>>(W2, b2, W3, b3);
    k_coords<<<196, 256>>>();
    k_epilogue<<<MQK, 256>>>(out);
}

// round 14
// speedup vs baseline: 1.3118x; 1.3118x over previous
#include <cuda_runtime.h>
#include <cstdint>

#define BATCH 256
#define SEQ   197
#define SN    196
#define DIM   768
#define GRID  14
#define MQK   (BATCH*SEQ)
#define MH    (BATCH*SN)
#define MV    (BATCH*64)
#define H60   60
#define K2    1536

__device__ float g_q [(size_t)MQK * DIM];
__device__ float g_k [(size_t)MQK * DIM];
__device__ float g_vs[(size_t)MV  * DIM];
__device__ float g_h1[(size_t)MH  * H60];
__device__ float g_sample[(size_t)MH * 2];

__device__ __forceinline__ uint32_t f2tf32(float f) {
    uint32_t u;
    asm("cvt.rna.tf32.f32 %0, %1;" : "=r"(u) : "f"(f));
    return u;
}

__device__ __forceinline__ void mma_tf32(float (&d)[4], const uint32_t (&a)[4], const uint32_t (&b)[2]) {
    asm volatile(
        "mma.sync.aligned.m16n8k8.row.col.f32.tf32.tf32.f32 "
        "{%0,%1,%2,%3}, {%4,%5,%6,%7}, {%8,%9}, {%0,%1,%2,%3};\n"
        : "+f"(d[0]), "+f"(d[1]), "+f"(d[2]), "+f"(d[3])
        : "r"(a[0]), "r"(a[1]), "r"(a[2]), "r"(a[3]), "r"(b[0]), "r"(b[1]));
}

__device__ __forceinline__ void ldsm_x4(uint32_t& r0, uint32_t& r1, uint32_t& r2, uint32_t& r3, uint32_t addr) {
    asm volatile("ldmatrix.sync.aligned.m8n8.x4.shared.b16 {%0,%1,%2,%3}, [%4];"
                 : "=r"(r0), "=r"(r1), "=r"(r2), "=r"(r3) : "r"(addr));
}

// ============================================================
// TF32 GEMM (round-6 proven body): Y = A@W^T + bias
// Block 128x128, K-step 32, 8 warps 2Mx4N, ldmatrix fragments,
// cvt-in-loop, register prefetch, static smem.
// Merged launch: bx < 4728 -> Q/K projection; else V projection.
//   qk: bx = rt*12 + (zz*6 + ct), col/z fastest (L2 reuse of X).
//   v:  bx' = bx-4728 = rt*6 + ct, rows map to 64 reachable tokens/batch.
// ============================================================
__global__ __launch_bounds__(256) void k_gemm_qkv(
    const float* __restrict__ X,
    const float* __restrict__ Wq, const float* __restrict__ bq,
    const float* __restrict__ Wk, const float* __restrict__ bk,
    const float* __restrict__ Wv, const float* __restrict__ bv)
{
    __shared__ __align__(16) uint32_t As[128][36];
    __shared__ __align__(16) uint32_t Bs[128][36];

    const int tid  = threadIdx.x;
    const int lane = tid & 31;
    const int wid  = tid >> 5;
    const int warpM = wid & 1;
    const int warpN = wid >> 1;

    const int ldr = tid >> 1;
    const int ldc = (tid & 1) * 16;

    const float* W;
    const float* bias;
    float*       Y;
    const float* Ap;
    int row0, col0;

    if (blockIdx.x < 4728) {
        const int bx  = blockIdx.x;
        const int rt  = bx / 12;
        const int rem = bx - rt * 12;
        const int ct  = rem % 6;
        const int zz  = rem / 6;
        W    = zz ? Wk : Wq;
        bias = zz ? bk : bq;
        Y    = zz ? g_k : g_q;
        row0 = rt * 128;
        col0 = ct * 128;
        Ap = X + (size_t)(row0 + ldr) * DIM + ldc;
    } else {
        const int bx = blockIdx.x - 4728;
        const int rt = bx / 6;
        const int ct = bx - rt * 6;
        W    = Wv;
        bias = bv;
        Y    = g_vs;
        row0 = rt * 128;
        col0 = ct * 128;
        const int r_g = row0 + ldr;
        const int bb  = r_g >> 6;
        const int jj  = r_g & 63;
        const int token = 1 + (6 + (jj >> 3)) * GRID + (6 + (jj & 7));
        Ap = X + (size_t)(bb * SEQ + token) * DIM + ldc;
    }
    const float* Bp = W + (size_t)(col0 + ldr) * DIM + ldc;

    const uint32_t As_addr = (uint32_t)__cvta_generic_to_shared(&As[0][0]);
    const uint32_t Bs_addr = (uint32_t)__cvta_generic_to_shared(&Bs[0][0]);
    const uint32_t a_base = As_addr + (((warpM*64 + (lane & 15)) * 36 + ((lane >> 4) << 2)) << 2);
    const uint32_t b_base = Bs_addr + (((warpN*32 + (lane & 15)) * 36 + ((lane >> 4) << 2)) << 2);

    float acc[4][4][4];
    #pragma unroll
    for (int mt = 0; mt < 4; mt++)
        #pragma unroll
        for (int nt = 0; nt < 4; nt++)
            #pragma unroll
            for (int i = 0; i < 4; i++) acc[mt][nt][i] = 0.f;

    float4 ra[4], rb[4];
    #pragma unroll
    for (int i = 0; i < 4; i++) {
        ra[i] = *reinterpret_cast<const float4*>(Ap + i*4);
        rb[i] = *reinterpret_cast<const float4*>(Bp + i*4);
    }

    for (int k0 = 0; k0 < DIM; k0 += 32) {
        #pragma unroll
        for (int i = 0; i < 4; i++) {
            uint4 ua = make_uint4(f2tf32(ra[i].x), f2tf32(ra[i].y), f2tf32(ra[i].z), f2tf32(ra[i].w));
            uint4 ub = make_uint4(f2tf32(rb[i].x), f2tf32(rb[i].y), f2tf32(rb[i].z), f2tf32(rb[i].w));
            *reinterpret_cast<uint4*>(&As[ldr][ldc + i*4]) = ua;
            *reinterpret_cast<uint4*>(&Bs[ldr][ldc + i*4]) = ub;
        }
        __syncthreads();
        if (k0 + 32 < DIM) {
            #pragma unroll
            for (int i = 0; i < 4; i++) {
                ra[i] = *reinterpret_cast<const float4*>(Ap + k0 + 32 + i*4);
                rb[i] = *reinterpret_cast<const float4*>(Bp + k0 + 32 + i*4);
            }
        }
        #pragma unroll
        for (int ks = 0; ks < 4; ks++) {
            uint32_t af[4][4], bf[4][2];
            #pragma unroll
            for (int mt = 0; mt < 4; mt++)
                ldsm_x4(af[mt][0], af[mt][1], af[mt][2], af[mt][3],
                        a_base + ((mt*16*36 + ks*8) << 2));
            #pragma unroll
            for (int nt2 = 0; nt2 < 2; nt2++) {
                uint32_t r0, r1, r2, r3;
                ldsm_x4(r0, r1, r2, r3, b_base + ((nt2*16*36 + ks*8) << 2));
                bf[2*nt2  ][0] = r0; bf[2*nt2+1][0] = r1;
                bf[2*nt2  ][1] = r2; bf[2*nt2+1][1] = r3;
            }
            #pragma unroll
            for (int mt = 0; mt < 4; mt++)
                #pragma unroll
                for (int nt = 0; nt < 4; nt++)
                    mma_tf32(acc[mt][nt], af[mt], bf[nt]);
        }
        __syncthreads();
    }

    #pragma unroll
    for (int nt = 0; nt < 4; nt++) {
        const int c = col0 + warpN*32 + nt*8 + 2*(lane & 3);
        const float b0v = bias[c];
        const float b1v = bias[c + 1];
        #pragma unroll
        for (int mt = 0; mt < 4; mt++) {
            const int r = row0 + warpM*64 + mt*16 + (lane >> 2);
            float2 o0 = make_float2(acc[mt][nt][0] + b0v, acc[mt][nt][1] + b1v);
            float2 o1 = make_float2(acc[mt][nt][2] + b0v, acc[mt][nt][3] + b1v);
            *reinterpret_cast<float2*>(Y + (size_t)r * DIM + c)       = o0;
            *reinterpret_cast<float2*>(Y + (size_t)(r + 8) * DIM + c) = o1;
        }
    }
}

// ============================================================
// TF32 MLP layer 1 (round-6 proven body): h1 = relu(concat(q,k)@W1^T + b1)
// Block 128x64; 8 warps 4Mx2N; cvt-in-loop.
// ============================================================
__global__ __launch_bounds__(256) void k_gemm_h1_t(
    const float* __restrict__ W1, const float* __restrict__ b1)
{
    __shared__ __align__(16) uint32_t As[128][36];
    __shared__ __align__(16) uint32_t Bs[64][36];

    const int tid  = threadIdx.x;
    const int lane = tid & 31;
    const int wid  = tid >> 5;
    const int warpM = wid & 3;
    const int warpN = wid >> 2;

    const int row0 = blockIdx.x * 128;

    const int ldr = tid >> 1;
    const int ldc = (tid & 1) * 16;

    const int r_g = row0 + ldr;
    const int bb  = r_g / SN;
    const int tt  = r_g - bb * SN;
    const size_t aoff = (size_t)(bb * SEQ + tt + 1) * DIM + ldc;

    const int ldr2 = tid >> 2;
    const int ldc2 = (tid & 3) * 8;
    const bool bvalid = (ldr2 < H60);
    const float* Bp = W1 + (size_t)ldr2 * K2 + ldc2;

    const uint32_t As_addr = (uint32_t)__cvta_generic_to_shared(&As[0][0]);
    const uint32_t Bs_addr = (uint32_t)__cvta_generic_to_shared(&Bs[0][0]);
    const uint32_t a_base = As_addr + (((warpM*32 + (lane & 15)) * 36 + ((lane >> 4) << 2)) << 2);
    const uint32_t b_base = Bs_addr + (((warpN*32 + (lane & 15)) * 36 + ((lane >> 4) << 2)) << 2);

    float acc[2][4][4];
    #pragma unroll
    for (int mt = 0; mt < 2; mt++)
        #pragma unroll
        for (int nt = 0; nt < 4; nt++)
            #pragma unroll
            for (int i = 0; i < 4; i++) acc[mt][nt][i] = 0.f;

    float4 ra[4], rb[2];
    {
        const float* base = g_q + aoff;
        #pragma unroll
        for (int i = 0; i < 4; i++)
            ra[i] = *reinterpret_cast<const float4*>(base + i*4);
        #pragma unroll
        for (int i = 0; i < 2; i++)
            rb[i] = bvalid ? *reinterpret_cast<const float4*>(Bp + i*4)
                           : make_float4(0.f, 0.f, 0.f, 0.f);
    }

    for (int k0 = 0; k0 < K2; k0 += 32) {
        #pragma unroll
        for (int i = 0; i < 4; i++) {
            uint4 ua = make_uint4(f2tf32(ra[i].x), f2tf32(ra[i].y), f2tf32(ra[i].z), f2tf32(ra[i].w));
            *reinterpret_cast<uint4*>(&As[ldr][ldc + i*4]) = ua;
        }
        #pragma unroll
        for (int i = 0; i < 2; i++) {
            uint4 ub = make_uint4(f2tf32(rb[i].x), f2tf32(rb[i].y), f2tf32(rb[i].z), f2tf32(rb[i].w));
            *reinterpret_cast<uint4*>(&Bs[ldr2][ldc2 + i*4]) = ub;
        }
        __syncthreads();
        if (k0 + 32 < K2) {
            const int kn = k0 + 32;
            const float* base = (kn < DIM) ? (g_q + aoff + kn) : (g_k + aoff + kn - DIM);
            #pragma unroll
            for (int i = 0; i < 4; i++)
                ra[i] = *reinterpret_cast<const float4*>(base + i*4);
            #pragma unroll
            for (int i = 0; i < 2; i++)
                rb[i] = bvalid ? *reinterpret_cast<const float4*>(Bp + kn + i*4)
                               : make_float4(0.f, 0.f, 0.f, 0.f);
        }
        #pragma unroll
        for (int ks = 0; ks < 4; ks++) {
            uint32_t af[2][4], bf[4][2];
            #pragma unroll
            for (int mt = 0; mt < 2; mt++)
                ldsm_x4(af[mt][0], af[mt][1], af[mt][2], af[mt][3],
                        a_base + ((mt*16*36 + ks*8) << 2));
            #pragma unroll
            for (int nt2 = 0; nt2 < 2; nt2++) {
                uint32_t r0, r1, r2, r3;
                ldsm_x4(r0, r1, r2, r3, b_base + ((nt2*16*36 + ks*8) << 2));
                bf[2*nt2  ][0] = r0; bf[2*nt2+1][0] = r1;
                bf[2*nt2  ][1] = r2; bf[2*nt2+1][1] = r3;
            }
            #pragma unroll
            for (int mt = 0; mt < 2; mt++)
                #pragma unroll
                for (int nt = 0; nt < 4; nt++)
                    mma_tf32(acc[mt][nt], af[mt], bf[nt]);
        }
        __syncthreads();
    }

    #pragma unroll
    for (int nt = 0; nt < 4; nt++) {
        const int c = warpN*32 + nt*8 + 2*(lane & 3);
        const float b0v = (c     < H60) ? b1[c]     : 0.f;
        const float b1v = (c + 1 < H60) ? b1[c + 1] : 0.f;
        #pragma unroll
        for (int mt = 0; mt < 2; mt++) {
            const int r = row0 + warpM*32 + mt*16 + (lane >> 2);
            if (c < H60) {
                g_h1[(size_t)r * H60 + c]       = fmaxf(acc[mt][nt][0] + b0v, 0.f);
                g_h1[(size_t)(r + 8) * H60 + c] = fmaxf(acc[mt][nt][2] + b0v, 0.f);
            }
            if (c + 1 < H60) {
                g_h1[(size_t)r * H60 + c + 1]       = fmaxf(acc[mt][nt][1] + b1v, 0.f);
                g_h1[(size_t)(r + 8) * H60 + c + 1] = fmaxf(acc[mt][nt][3] + b1v, 0.f);
            }
        }
    }
}

// ============================================================
// MLP layers 2+3 (unchanged from best)
// ============================================================
__global__ __launch_bounds__(256) void k_mlp23(
    const float* __restrict__ W2, const float* __restrict__ b2,
    const float* __restrict__ W3, const float* __restrict__ b3)
{
    __shared__ float W2s[60*61], W3s[120], b2s[60], b3s[2], h1s[16][60], h2s[16][60];
    const int tid = threadIdx.x;
    for (int i = tid; i < 3600; i += 256) { int rr = i / 60, cc = i - rr * 60; W2s[rr*61+cc] = W2[i]; }
    if (tid < 120) W3s[tid] = W3[tid];
    if (tid < 60)  b2s[tid] = b2[tid];
    if (tid < 2)   b3s[tid] = b3[tid];
    const int r0 = blockIdx.x * 16;
    for (int i = tid; i < 960; i += 256) { int t = i / 60, c = i - t * 60; h1s[t][c] = g_h1[(size_t)(r0+t)*H60 + c]; }
    __syncthreads();
    const int tg = tid >> 6, f = tid & 63;
    if (f < H60) {
        float a0 = b2s[f], a1 = a0, a2 = a0, a3 = a0;
        #pragma unroll 4
        for (int g = 0; g < H60; g++) {
            const float w = W2s[f*61 + g];
            a0 = fmaf(w, h1s[tg*4+0][g], a0); a1 = fmaf(w, h1s[tg*4+1][g], a1);
            a2 = fmaf(w, h1s[tg*4+2][g], a2); a3 = fmaf(w, h1s[tg*4+3][g], a3);
        }
        h2s[tg*4+0][f] = fmaxf(a0, 0.f); h2s[tg*4+1][f] = fmaxf(a1, 0.f);
        h2s[tg*4+2][f] = fmaxf(a2, 0.f); h2s[tg*4+3][f] = fmaxf(a3, 0.f);
    }
    __syncthreads();
    if (tid < 32) {
        int t2 = tid >> 1, c = tid & 1;
        float s = b3s[c];
        #pragma unroll 4
        for (int g = 0; g < H60; g++) s = fmaf(W3s[c*60+g], h2s[t2][g], s);
        g_sample[(size_t)(r0+t2)*2 + c] = 1.f / (1.f + expf(-s));
    }
}

// ============================================================
// Epilogue: warp per (b,s). Coords computed inline from g_sample.
// score = dot(sk, q); out = sigmoid(0.01*score) * sv; CLS: sk=sv=1.
// 8 warps/block, grid 6304 (= 50432/8), no block-level sync.
// ============================================================
__global__ __launch_bounds__(256) void k_epilogue(float* __restrict__ out)
{
    const int bs   = blockIdx.x * 8 + (threadIdx.x >> 5);   // 0..50431
    const int lane = threadIdx.x & 31;
    const int b = bs / SEQ, s = bs - b * SEQ;
    const size_t qbase = (size_t)bs * DIM;

    float  w[4];
    size_t rowk[4], rowv[4];
    bool   vk[4], vv[4];

    if (s > 0) {
        const int p = s - 1;
        const int q1 = 2 * p, q2 = 2 * p + 1;
        const float gx = (q1 < SN) ? g_sample[(size_t)(b*SN+q1)*2+0]
                                   : g_sample[(size_t)(b*SN+q1-SN)*2+1];
        const float gy = (q2 < SN) ? g_sample[(size_t)(b*SN+q2)*2+0]
                                   : g_sample[(size_t)(b*SN+q2-SN)*2+1];
        const float ix = ((gx + 1.f) * (float)GRID - 1.f) * 0.5f;
        const float iy = ((gy + 1.f) * (float)GRID - 1.f) * 0.5f;
        const float ix0f = floorf(ix), iy0f = floorf(iy);
        const float wx1 = ix - ix0f, wx0 = 1.f - wx1;
        const float wy1 = iy - iy0f, wy0 = 1.f - wy1;
        const int x0 = (int)ix0f, y0 = (int)iy0f;
        const int xs[4] = {x0, x0+1, x0, x0+1};
        const int ys[4] = {y0, y0, y0+1, y0+1};
        const float ws[4] = {wy0*wx0, wy0*wx1, wy1*wx0, wy1*wx1};
        #pragma unroll
        for (int c = 0; c < 4; c++) {
            const int x = xs[c], y = ys[c];
            const bool v = (x >= 0) && (x <= GRID-1) && (y >= 0) && (y <= GRID-1);
            vk[c] = v; w[c] = ws[c];
            rowk[c] = v ? (size_t)(b * SEQ + 1 + y * GRID + x) * DIM : 0;
            const bool v2 = v && (x >= 6) && (y >= 6);
            vv[c] = v2;
            rowv[c] = v2 ? (size_t)(b * 64 + (y-6)*8 + (x-6)) * DIM : 0;
        }
    }

    float part = 0.f;
    float svreg[24];
    #pragma unroll
    for (int it = 0; it < 24; it++) {
        const int d = lane + it * 32;
        float skd, svd;
        if (s == 0) { skd = 1.f; svd = 1.f; }
        else {
            skd = 0.f; svd = 0.f;
            #pragma unroll
            for (int c = 0; c < 4; c++) {
                if (vk[c]) skd = fmaf(w[c], g_k[rowk[c] + d], skd);
                if (vv[c]) svd = fmaf(w[c], g_vs[rowv[c] + d], svd);
            }
        }
        svreg[it] = svd;
        part = fmaf(skd, g_q[qbase + d], part);
    }
    #pragma unroll
    for (int off = 16; off > 0; off >>= 1)
        part += __shfl_xor_sync(0xffffffffu, part, off);
    const float sg = 1.f / (1.f + expf(-0.01f * part));
    #pragma unroll
    for (int it = 0; it < 24; it++)
        out[qbase + lane + it * 32] = sg * svreg[it];
}

// ============================================================
extern "C" void kernel_launch(void* const* d_in, const int* in_sizes, int n_in,
                              void* d_out, int out_size)
{
    const float* x  = (const float*)d_in[0];
    const float* Wq = (const float*)d_in[2];  const float* bq = (const float*)d_in[3];
    const float* Wk = (const float*)d_in[4];  const float* bk = (const float*)d_in[5];
    const float* Wv = (const float*)d_in[6];  const float* bv = (const float*)d_in[7];
    const float* W1 = (const float*)d_in[8];  const float* b1 = (const float*)d_in[9];
    const float* W2 = (const float*)d_in[10]; const float* b2 = (const float*)d_in[11];
    const float* W3 = (const float*)d_in[12]; const float* b3 = (const float*)d_in[13];
    float* out = (float*)d_out;

    // Q,K (394*12 blocks) + V (128*6 blocks) merged in one launch
    k_gemm_qkv<<<394 * 12 + 128 * 6, 256>>>(x, Wq, bq, Wk, bk, Wv, bv);
    // MLP layer 1 (reads g_q, g_k)
    k_gemm_h1_t<<<392, 256>>>(W1, b1);
    // MLP layers 2+3 -> sample
    k_mlp23<<<3136, 256>>>(W2, b2, W3, b3);
    // bilinear sample + scores + output (coords inline, warp per row)
    k_epilogue<<<MQK / 8, 256>>>(out);
}

// round 15
// speedup vs baseline: 1.7914x; 1.3656x over previous
#include <cuda_runtime.h>
#include <cstdint>

#define BATCH 256
#define SEQ   197
#define SN    196
#define DIM   768
#define GRID  14
#define MQK   (BATCH*SEQ)
#define MH    (BATCH*SN)
#define MV    (BATCH*64)
#define H60   60
#define K2    1536

__device__ float g_q [(size_t)MQK * DIM];
__device__ float g_k [(size_t)MQK * DIM];
__device__ float g_vs[(size_t)MV  * DIM];
__device__ float g_h1[(size_t)MH  * H60];
__device__ float g_sample[(size_t)MH * 2];
__device__ float g_coords[(size_t)MH * 2];

__device__ __forceinline__ uint32_t f2tf32(float f) {
    uint32_t u;
    asm("cvt.rna.tf32.f32 %0, %1;" : "=r"(u) : "f"(f));
    return u;
}

__device__ __forceinline__ void mma_tf32(float (&d)[4], const uint32_t (&a)[4], const uint32_t (&b)[2]) {
    asm volatile(
        "mma.sync.aligned.m16n8k8.row.col.f32.tf32.tf32.f32 "
        "{%0,%1,%2,%3}, {%4,%5,%6,%7}, {%8,%9}, {%0,%1,%2,%3};\n"
        : "+f"(d[0]), "+f"(d[1]), "+f"(d[2]), "+f"(d[3])
        : "r"(a[0]), "r"(a[1]), "r"(a[2]), "r"(a[3]), "r"(b[0]), "r"(b[1]));
}

__device__ __forceinline__ void ldsm_x4(uint32_t& r0, uint32_t& r1, uint32_t& r2, uint32_t& r3, uint32_t addr) {
    asm volatile("ldmatrix.sync.aligned.m8n8.x4.shared.b16 {%0,%1,%2,%3}, [%4];"
                 : "=r"(r0), "=r"(r1), "=r"(r2), "=r"(r3) : "r"(addr));
}

// ============================================================
// TF32 tensor-core GEMM (round-6 proven): Y[r,e] = sum_d A[r,d]*W[e,d] + bias
// Block 128x128, K-step 32. 8 warps = 2(M) x 4(N); warp tile 64x32.
// 1-D grid: blockIdx.x = rowTile*12 + (z*6 + colTile) -- col/z fastest.
// ============================================================
__global__ __launch_bounds__(256) void k_gemm_qk_t(
    const float* __restrict__ X,
    const float* __restrict__ Wq, const float* __restrict__ bq,
    const float* __restrict__ Wk, const float* __restrict__ bk)
{
    const int bx  = blockIdx.x;
    const int rt  = bx / 12;
    const int rem = bx - rt * 12;
    const int ct  = rem % 6;
    const int zz  = rem / 6;

    const float* W    = zz ? Wk : Wq;
    const float* bias = zz ? bk : bq;
    float*       Y    = zz ? g_k : g_q;

    __shared__ __align__(16) uint32_t As[128][36];
    __shared__ __align__(16) uint32_t Bs[128][36];

    const int tid  = threadIdx.x;
    const int lane = tid & 31;
    const int wid  = tid >> 5;
    const int warpM = wid & 1;
    const int warpN = wid >> 1;

    const int row0 = rt * 128;
    const int col0 = ct * 128;

    const int ldr = tid >> 1;
    const int ldc = (tid & 1) * 16;

    const float* Ap = X + (size_t)(row0 + ldr) * DIM + ldc;
    const float* Bp = W + (size_t)(col0 + ldr) * DIM + ldc;

    const uint32_t As_addr = (uint32_t)__cvta_generic_to_shared(&As[0][0]);
    const uint32_t Bs_addr = (uint32_t)__cvta_generic_to_shared(&Bs[0][0]);
    const uint32_t a_base = As_addr + (((warpM*64 + (lane & 15)) * 36 + ((lane >> 4) << 2)) << 2);
    const uint32_t b_base = Bs_addr + (((warpN*32 + (lane & 15)) * 36 + ((lane >> 4) << 2)) << 2);

    float acc[4][4][4];
    #pragma unroll
    for (int mt = 0; mt < 4; mt++)
        #pragma unroll
        for (int nt = 0; nt < 4; nt++)
            #pragma unroll
            for (int i = 0; i < 4; i++) acc[mt][nt][i] = 0.f;

    float4 ra[4], rb[4];
    #pragma unroll
    for (int i = 0; i < 4; i++) {
        ra[i] = *reinterpret_cast<const float4*>(Ap + i*4);
        rb[i] = *reinterpret_cast<const float4*>(Bp + i*4);
    }

    for (int k0 = 0; k0 < DIM; k0 += 32) {
        #pragma unroll
        for (int i = 0; i < 4; i++) {
            uint4 ua = make_uint4(f2tf32(ra[i].x), f2tf32(ra[i].y), f2tf32(ra[i].z), f2tf32(ra[i].w));
            uint4 ub = make_uint4(f2tf32(rb[i].x), f2tf32(rb[i].y), f2tf32(rb[i].z), f2tf32(rb[i].w));
            *reinterpret_cast<uint4*>(&As[ldr][ldc + i*4]) = ua;
            *reinterpret_cast<uint4*>(&Bs[ldr][ldc + i*4]) = ub;
        }
        __syncthreads();
        if (k0 + 32 < DIM) {
            #pragma unroll
            for (int i = 0; i < 4; i++) {
                ra[i] = *reinterpret_cast<const float4*>(Ap + k0 + 32 + i*4);
                rb[i] = *reinterpret_cast<const float4*>(Bp + k0 + 32 + i*4);
            }
        }
        #pragma unroll
        for (int ks = 0; ks < 4; ks++) {
            uint32_t af[4][4], bf[4][2];
            #pragma unroll
            for (int mt = 0; mt < 4; mt++)
                ldsm_x4(af[mt][0], af[mt][1], af[mt][2], af[mt][3],
                        a_base + ((mt*16*36 + ks*8) << 2));
            #pragma unroll
            for (int nt2 = 0; nt2 < 2; nt2++) {
                uint32_t r0, r1, r2, r3;
                ldsm_x4(r0, r1, r2, r3, b_base + ((nt2*16*36 + ks*8) << 2));
                bf[2*nt2  ][0] = r0; bf[2*nt2+1][0] = r1;
                bf[2*nt2  ][1] = r2; bf[2*nt2+1][1] = r3;
            }
            #pragma unroll
            for (int mt = 0; mt < 4; mt++)
                #pragma unroll
                for (int nt = 0; nt < 4; nt++)
                    mma_tf32(acc[mt][nt], af[mt], bf[nt]);
        }
        __syncthreads();
    }

    #pragma unroll
    for (int nt = 0; nt < 4; nt++) {
        const int c = col0 + warpN*32 + nt*8 + 2*(lane & 3);
        const float b0v = bias[c];
        const float b1v = bias[c + 1];
        #pragma unroll
        for (int mt = 0; mt < 4; mt++) {
            const int r = row0 + warpM*64 + mt*16 + (lane >> 2);
            float2 o0 = make_float2(acc[mt][nt][0] + b0v, acc[mt][nt][1] + b1v);
            float2 o1 = make_float2(acc[mt][nt][2] + b0v, acc[mt][nt][3] + b1v);
            *reinterpret_cast<float2*>(Y + (size_t)r * DIM + c)       = o0;
            *reinterpret_cast<float2*>(Y + (size_t)(r + 8) * DIM + c) = o1;
        }
    }
}

// ============================================================
// TF32 V projection (round-6 proven): 64 reachable tokens per batch.
// ============================================================
__global__ __launch_bounds__(256) void k_gemm_v_t(
    const float* __restrict__ X,
    const float* __restrict__ Wv, const float* __restrict__ bv)
{
    __shared__ __align__(16) uint32_t As[128][36];
    __shared__ __align__(16) uint32_t Bs[128][36];

    const int bx = blockIdx.x;
    const int rt = bx / 6;
    const int ct = bx - rt * 6;

    const int tid  = threadIdx.x;
    const int lane = tid & 31;
    const int wid  = tid >> 5;
    const int warpM = wid & 1;
    const int warpN = wid >> 1;

    const int row0 = rt * 128;
    const int col0 = ct * 128;

    const int ldr = tid >> 1;
    const int ldc = (tid & 1) * 16;

    const int r_g = row0 + ldr;
    const int bb  = r_g >> 6;
    const int jj  = r_g & 63;
    const int token = 1 + (6 + (jj >> 3)) * GRID + (6 + (jj & 7));
    const float* Ap = X + (size_t)(bb * SEQ + token) * DIM + ldc;
    const float* Bp = Wv + (size_t)(col0 + ldr) * DIM + ldc;

    const uint32_t As_addr = (uint32_t)__cvta_generic_to_shared(&As[0][0]);
    const uint32_t Bs_addr = (uint32_t)__cvta_generic_to_shared(&Bs[0][0]);
    const uint32_t a_base = As_addr + (((warpM*64 + (lane & 15)) * 36 + ((lane >> 4) << 2)) << 2);
    const uint32_t b_base = Bs_addr + (((warpN*32 + (lane & 15)) * 36 + ((lane >> 4) << 2)) << 2);

    float acc[4][4][4];
    #pragma unroll
    for (int mt = 0; mt < 4; mt++)
        #pragma unroll
        for (int nt = 0; nt < 4; nt++)
            #pragma unroll
            for (int i = 0; i < 4; i++) acc[mt][nt][i] = 0.f;

    float4 ra[4], rb[4];
    #pragma unroll
    for (int i = 0; i < 4; i++) {
        ra[i] = *reinterpret_cast<const float4*>(Ap + i*4);
        rb[i] = *reinterpret_cast<const float4*>(Bp + i*4);
    }

    for (int k0 = 0; k0 < DIM; k0 += 32) {
        #pragma unroll
        for (int i = 0; i < 4; i++) {
            uint4 ua = make_uint4(f2tf32(ra[i].x), f2tf32(ra[i].y), f2tf32(ra[i].z), f2tf32(ra[i].w));
            uint4 ub = make_uint4(f2tf32(rb[i].x), f2tf32(rb[i].y), f2tf32(rb[i].z), f2tf32(rb[i].w));
            *reinterpret_cast<uint4*>(&As[ldr][ldc + i*4]) = ua;
            *reinterpret_cast<uint4*>(&Bs[ldr][ldc + i*4]) = ub;
        }
        __syncthreads();
        if (k0 + 32 < DIM) {
            #pragma unroll
            for (int i = 0; i < 4; i++) {
                ra[i] = *reinterpret_cast<const float4*>(Ap + k0 + 32 + i*4);
                rb[i] = *reinterpret_cast<const float4*>(Bp + k0 + 32 + i*4);
            }
        }
        #pragma unroll
        for (int ks = 0; ks < 4; ks++) {
            uint32_t af[4][4], bf[4][2];
            #pragma unroll
            for (int mt = 0; mt < 4; mt++)
                ldsm_x4(af[mt][0], af[mt][1], af[mt][2], af[mt][3],
                        a_base + ((mt*16*36 + ks*8) << 2));
            #pragma unroll
            for (int nt2 = 0; nt2 < 2; nt2++) {
                uint32_t r0, r1, r2, r3;
                ldsm_x4(r0, r1, r2, r3, b_base + ((nt2*16*36 + ks*8) << 2));
                bf[2*nt2  ][0] = r0; bf[2*nt2+1][0] = r1;
                bf[2*nt2  ][1] = r2; bf[2*nt2+1][1] = r3;
            }
            #pragma unroll
            for (int mt = 0; mt < 4; mt++)
                #pragma unroll
                for (int nt = 0; nt < 4; nt++)
                    mma_tf32(acc[mt][nt], af[mt], bf[nt]);
        }
        __syncthreads();
    }

    #pragma unroll
    for (int nt = 0; nt < 4; nt++) {
        const int c = col0 + warpN*32 + nt*8 + 2*(lane & 3);
        const float b0v = bv[c];
        const float b1v = bv[c + 1];
        #pragma unroll
        for (int mt = 0; mt < 4; mt++) {
            const int r = row0 + warpM*64 + mt*16 + (lane >> 2);
            float2 o0 = make_float2(acc[mt][nt][0] + b0v, acc[mt][nt][1] + b1v);
            float2 o1 = make_float2(acc[mt][nt][2] + b0v, acc[mt][nt][3] + b1v);
            *reinterpret_cast<float2*>(g_vs + (size_t)r * DIM + c)       = o0;
            *reinterpret_cast<float2*>(g_vs + (size_t)(r + 8) * DIM + c) = o1;
        }
    }
}

// ============================================================
// TF32 MLP layer 1 (round-6 proven): h1 = relu(concat(q,k)@W1^T + b1)
// ============================================================
__global__ __launch_bounds__(256) void k_gemm_h1_t(
    const float* __restrict__ W1, const float* __restrict__ b1)
{
    __shared__ __align__(16) uint32_t As[128][36];
    __shared__ __align__(16) uint32_t Bs[64][36];

    const int tid  = threadIdx.x;
    const int lane = tid & 31;
    const int wid  = tid >> 5;
    const int warpM = wid & 3;
    const int warpN = wid >> 2;

    const int row0 = blockIdx.x * 128;

    const int ldr = tid >> 1;
    const int ldc = (tid & 1) * 16;

    const int r_g = row0 + ldr;
    const int bb  = r_g / SN;
    const int tt  = r_g - bb * SN;
    const size_t aoff = (size_t)(bb * SEQ + tt + 1) * DIM + ldc;

    const int ldr2 = tid >> 2;
    const int ldc2 = (tid & 3) * 8;
    const bool bvalid = (ldr2 < H60);
    const float* Bp = W1 + (size_t)ldr2 * K2 + ldc2;

    const uint32_t As_addr = (uint32_t)__cvta_generic_to_shared(&As[0][0]);
    const uint32_t Bs_addr = (uint32_t)__cvta_generic_to_shared(&Bs[0][0]);
    const uint32_t a_base = As_addr + (((warpM*32 + (lane & 15)) * 36 + ((lane >> 4) << 2)) << 2);
    const uint32_t b_base = Bs_addr + (((warpN*32 + (lane & 15)) * 36 + ((lane >> 4) << 2)) << 2);

    float acc[2][4][4];
    #pragma unroll
    for (int mt = 0; mt < 2; mt++)
        #pragma unroll
        for (int nt = 0; nt < 4; nt++)
            #pragma unroll
            for (int i = 0; i < 4; i++) acc[mt][nt][i] = 0.f;

    float4 ra[4], rb[2];
    {
        const float* base = g_q + aoff;
        #pragma unroll
        for (int i = 0; i < 4; i++)
            ra[i] = *reinterpret_cast<const float4*>(base + i*4);
        #pragma unroll
        for (int i = 0; i < 2; i++)
            rb[i] = bvalid ? *reinterpret_cast<const float4*>(Bp + i*4)
                           : make_float4(0.f, 0.f, 0.f, 0.f);
    }

    for (int k0 = 0; k0 < K2; k0 += 32) {
        #pragma unroll
        for (int i = 0; i < 4; i++) {
            uint4 ua = make_uint4(f2tf32(ra[i].x), f2tf32(ra[i].y), f2tf32(ra[i].z), f2tf32(ra[i].w));
            *reinterpret_cast<uint4*>(&As[ldr][ldc + i*4]) = ua;
        }
        #pragma unroll
        for (int i = 0; i < 2; i++) {
            uint4 ub = make_uint4(f2tf32(rb[i].x), f2tf32(rb[i].y), f2tf32(rb[i].z), f2tf32(rb[i].w));
            *reinterpret_cast<uint4*>(&Bs[ldr2][ldc2 + i*4]) = ub;
        }
        __syncthreads();
        if (k0 + 32 < K2) {
            const int kn = k0 + 32;
            const float* base = (kn < DIM) ? (g_q + aoff + kn) : (g_k + aoff + kn - DIM);
            #pragma unroll
            for (int i = 0; i < 4; i++)
                ra[i] = *reinterpret_cast<const float4*>(base + i*4);
            #pragma unroll
            for (int i = 0; i < 2; i++)
                rb[i] = bvalid ? *reinterpret_cast<const float4*>(Bp + kn + i*4)
                               : make_float4(0.f, 0.f, 0.f, 0.f);
        }
        #pragma unroll
        for (int ks = 0; ks < 4; ks++) {
            uint32_t af[2][4], bf[4][2];
            #pragma unroll
            for (int mt = 0; mt < 2; mt++)
                ldsm_x4(af[mt][0], af[mt][1], af[mt][2], af[mt][3],
                        a_base + ((mt*16*36 + ks*8) << 2));
            #pragma unroll
            for (int nt2 = 0; nt2 < 2; nt2++) {
                uint32_t r0, r1, r2, r3;
                ldsm_x4(r0, r1, r2, r3, b_base + ((nt2*16*36 + ks*8) << 2));
                bf[2*nt2  ][0] = r0; bf[2*nt2+1][0] = r1;
                bf[2*nt2  ][1] = r2; bf[2*nt2+1][1] = r3;
            }
            #pragma unroll
            for (int mt = 0; mt < 2; mt++)
                #pragma unroll
                for (int nt = 0; nt < 4; nt++)
                    mma_tf32(acc[mt][nt], af[mt], bf[nt]);
        }
        __syncthreads();
    }

    #pragma unroll
    for (int nt = 0; nt < 4; nt++) {
        const int c = warpN*32 + nt*8 + 2*(lane & 3);
        const float b0v = (c     < H60) ? b1[c]     : 0.f;
        const float b1v = (c + 1 < H60) ? b1[c + 1] : 0.f;
        #pragma unroll
        for (int mt = 0; mt < 2; mt++) {
            const int r = row0 + warpM*32 + mt*16 + (lane >> 2);
            if (c < H60) {
                g_h1[(size_t)r * H60 + c]       = fmaxf(acc[mt][nt][0] + b0v, 0.f);
                g_h1[(size_t)(r + 8) * H60 + c] = fmaxf(acc[mt][nt][2] + b0v, 0.f);
            }
            if (c + 1 < H60) {
                g_h1[(size_t)r * H60 + c + 1]       = fmaxf(acc[mt][nt][1] + b1v, 0.f);
                g_h1[(size_t)(r + 8) * H60 + c + 1] = fmaxf(acc[mt][nt][3] + b1v, 0.f);
            }
        }
    }
}

// ============================================================
// MLP layers 2+3 (unchanged)
// ============================================================
__global__ __launch_bounds__(256) void k_mlp23(
    const float* __restrict__ W2, const float* __restrict__ b2,
    const float* __restrict__ W3, const float* __restrict__ b3)
{
    __shared__ float W2s[60*61], W3s[120], b2s[60], b3s[2], h1s[16][60], h2s[16][60];
    const int tid = threadIdx.x;
    for (int i = tid; i < 3600; i += 256) { int rr = i / 60, cc = i - rr * 60; W2s[rr*61+cc] = W2[i]; }
    if (tid < 120) W3s[tid] = W3[tid];
    if (tid < 60)  b2s[tid] = b2[tid];
    if (tid < 2)   b3s[tid] = b3[tid];
    const int r0 = blockIdx.x * 16;
    for (int i = tid; i < 960; i += 256) { int t = i / 60, c = i - t * 60; h1s[t][c] = g_h1[(size_t)(r0+t)*H60 + c]; }
    __syncthreads();
    const int tg = tid >> 6, f = tid & 63;
    if (f < H60) {
        float a0 = b2s[f], a1 = a0, a2 = a0, a3 = a0;
        #pragma unroll 4
        for (int g = 0; g < H60; g++) {
            const float w = W2s[f*61 + g];
            a0 = fmaf(w, h1s[tg*4+0][g], a0); a1 = fmaf(w, h1s[tg*4+1][g], a1);
            a2 = fmaf(w, h1s[tg*4+2][g], a2); a3 = fmaf(w, h1s[tg*4+3][g], a3);
        }
        h2s[tg*4+0][f] = fmaxf(a0, 0.f); h2s[tg*4+1][f] = fmaxf(a1, 0.f);
        h2s[tg*4+2][f] = fmaxf(a2, 0.f); h2s[tg*4+3][f] = fmaxf(a3, 0.f);
    }
    __syncthreads();
    if (tid < 32) {
        int t2 = tid >> 1, c = tid & 1;
        float s = b3s[c];
        #pragma unroll 4
        for (int g = 0; g < H60; g++) s = fmaf(W3s[c*60+g], h2s[t2][g], s);
        g_sample[(size_t)(r0+t2)*2 + c] = 1.f / (1.f + expf(-s));
    }
}

// ============================================================
// Grid coordinate shuffle + unnormalize (unchanged)
// ============================================================
__global__ void k_coords()
{
    const int id = blockIdx.x * 256 + threadIdx.x;
    const int b = id / SN, p = id - b * SN;
    const int q1 = 2 * p, q2 = 2 * p + 1;
    float gx = (q1 < SN) ? g_sample[(size_t)(b*SN+q1)*2+0] : g_sample[(size_t)(b*SN+q1-SN)*2+1];
    float gy = (q2 < SN) ? g_sample[(size_t)(b*SN+q2)*2+0] : g_sample[(size_t)(b*SN+q2-SN)*2+1];
    g_coords[(size_t)id*2+0] = ((gx + 1.f) * (float)GRID - 1.f) * 0.5f;
    g_coords[(size_t)id*2+1] = ((gy + 1.f) * (float)GRID - 1.f) * 0.5f;
}

// ============================================================
// Epilogue: 192 threads per (b,s) row, all-float4 (768 = 192*4).
// 8 gathered float4 loads + 1 q float4 per thread; butterfly+smem reduce.
// ============================================================
__global__ __launch_bounds__(192) void k_epilogue(float* __restrict__ out)
{
    const int bs = blockIdx.x;              // 0..50431
    const int b  = bs / SEQ;
    const int s  = bs - b * SEQ;
    const int tid = threadIdx.x;            // 0..191
    const int lane = tid & 31;
    const int wid  = tid >> 5;              // 0..5
    __shared__ float red[6];
    __shared__ float sigsh;

    const size_t qbase = (size_t)bs * DIM;
    const int d0 = tid * 4;

    float  w[4];
    size_t rowk[4], rowv[4];
    bool   vk[4], vv[4];

    if (s > 0) {
        const int p = s - 1;
        const float ix = g_coords[(size_t)(b*SN + p)*2 + 0];
        const float iy = g_coords[(size_t)(b*SN + p)*2 + 1];
        const float ix0f = floorf(ix), iy0f = floorf(iy);
        const float wx1 = ix - ix0f, wx0 = 1.f - wx1;
        const float wy1 = iy - iy0f, wy0 = 1.f - wy1;
        const int x0 = (int)ix0f, y0 = (int)iy0f;
        const int xs[4] = {x0, x0+1, x0, x0+1};
        const int ys[4] = {y0, y0, y0+1, y0+1};
        const float ws[4] = {wy0*wx0, wy0*wx1, wy1*wx0, wy1*wx1};
        #pragma unroll
        for (int c = 0; c < 4; c++) {
            const int x = xs[c], y = ys[c];
            const bool v = (x >= 0) && (x <= GRID-1) && (y >= 0) && (y <= GRID-1);
            vk[c] = v; w[c] = ws[c];
            rowk[c] = v ? (size_t)(b * SEQ + 1 + y * GRID + x) * DIM : 0;
            const bool v2 = v && (x >= 6) && (y >= 6);
            vv[c] = v2;
            rowv[c] = v2 ? (size_t)(b * 64 + (y-6)*8 + (x-6)) * DIM : 0;
        }
    }

    float4 sk4, sv4;
    if (s == 0) {
        sk4 = make_float4(1.f, 1.f, 1.f, 1.f);
        sv4 = make_float4(1.f, 1.f, 1.f, 1.f);
    } else {
        sk4 = make_float4(0.f, 0.f, 0.f, 0.f);
        sv4 = make_float4(0.f, 0.f, 0.f, 0.f);
        #pragma unroll
        for (int c = 0; c < 4; c++) {
            if (vk[c]) {
                const float4 kv = *reinterpret_cast<const float4*>(g_k + rowk[c] + d0);
                sk4.x = fmaf(w[c], kv.x, sk4.x); sk4.y = fmaf(w[c], kv.y, sk4.y);
                sk4.z = fmaf(w[c], kv.z, sk4.z); sk4.w = fmaf(w[c], kv.w, sk4.w);
            }
            if (vv[c]) {
                const float4 vv4 = *reinterpret_cast<const float4*>(g_vs + rowv[c] + d0);
                sv4.x = fmaf(w[c], vv4.x, sv4.x); sv4.y = fmaf(w[c], vv4.y, sv4.y);
                sv4.z = fmaf(w[c], vv4.z, sv4.z); sv4.w = fmaf(w[c], vv4.w, sv4.w);
            }
        }
    }

    const float4 q4 = *reinterpret_cast<const float4*>(g_q + qbase + d0);
    float part = fmaf(sk4.x, q4.x, fmaf(sk4.y, q4.y, fmaf(sk4.z, q4.z, sk4.w * q4.w)));

    #pragma unroll
    for (int off = 16; off > 0; off >>= 1)
        part += __shfl_xor_sync(0xffffffffu, part, off);
    if (lane == 0) red[wid] = part;
    __syncthreads();
    if (tid == 0) {
        float sum = red[0] + red[1] + red[2] + red[3] + red[4] + red[5];
        sigsh = 1.f / (1.f + expf(-0.01f * sum));
    }
    __syncthreads();
    const float sg = sigsh;
    float4 o = make_float4(sg * sv4.x, sg * sv4.y, sg * sv4.z, sg * sv4.w);
    *reinterpret_cast<float4*>(out + qbase + d0) = o;
}

// ============================================================
extern "C" void kernel_launch(void* const* d_in, const int* in_sizes, int n_in,
                              void* d_out, int out_size)
{
    const float* x  = (const float*)d_in[0];
    const float* Wq = (const float*)d_in[2];  const float* bq = (const float*)d_in[3];
    const float* Wk = (const float*)d_in[4];  const float* bk = (const float*)d_in[5];
    const float* Wv = (const float*)d_in[6];  const float* bv = (const float*)d_in[7];
    const float* W1 = (const float*)d_in[8];  const float* b1 = (const float*)d_in[9];
    const float* W2 = (const float*)d_in[10]; const float* b2 = (const float*)d_in[11];
    const float* W3 = (const float*)d_in[12]; const float* b3 = (const float*)d_in[13];
    float* out = (float*)d_out;

    k_gemm_qk_t<<<394 * 12, 256>>>(x, Wq, bq, Wk, bk);
    k_gemm_v_t<<<128 * 6, 256>>>(x, Wv, bv);
    k_gemm_h1_t<<<392, 256>>>(W1, b1);
    k_mlp23<<<3136, 256>>>(W2, b2, W3, b3);
    k_coords<<<196, 256>>>();
    k_epilogue<<<MQK, 192>>>(out);
}

// round 16
// speedup vs baseline: 1.9045x; 1.0631x over previous
#include <cuda_runtime.h>
#include <cstdint>

#define BATCH 256
#define SEQ   197
#define SN    196
#define DIM   768
#define GRID  14
#define MQK   (BATCH*SEQ)
#define MH    (BATCH*SN)
#define MV    (BATCH*64)
#define H60   60
#define K2    1536

__device__ float g_q  [(size_t)MQK * DIM];
__device__ float g_kr [(size_t)MV  * DIM];
__device__ float g_vs [(size_t)MV  * DIM];
__device__ float g_h1 [(size_t)MH  * H60];
__device__ float g_sample[(size_t)MH * 2];
__device__ float g_coords[(size_t)MH * 2];
__device__ float g_weff[(size_t)H60 * DIM];
__device__ float g_beff[H60];

__device__ __forceinline__ uint32_t f2tf32(float f) {
    uint32_t u;
    asm("cvt.rna.tf32.f32 %0, %1;" : "=r"(u) : "f"(f));
    return u;
}

__device__ __forceinline__ void mma_tf32(float (&d)[4], const uint32_t (&a)[4], const uint32_t (&b)[2]) {
    asm volatile(
        "mma.sync.aligned.m16n8k8.row.col.f32.tf32.tf32.f32 "
        "{%0,%1,%2,%3}, {%4,%5,%6,%7}, {%8,%9}, {%0,%1,%2,%3};\n"
        : "+f"(d[0]), "+f"(d[1]), "+f"(d[2]), "+f"(d[3])
        : "r"(a[0]), "r"(a[1]), "r"(a[2]), "r"(a[3]), "r"(b[0]), "r"(b[1]));
}

__device__ __forceinline__ void ldsm_x4(uint32_t& r0, uint32_t& r1, uint32_t& r2, uint32_t& r3, uint32_t addr) {
    asm volatile("ldmatrix.sync.aligned.m8n8.x4.shared.b16 {%0,%1,%2,%3}, [%4];"
                 : "=r"(r0), "=r"(r1), "=r"(r2), "=r"(r3) : "r"(addr));
}

// ============================================================
// Weff[f][d] = sum_e W1[f][e]*Wq[e][d] + W1[f][768+e]*Wk[e][d]
// 60 blocks (one per f), 256 threads, 3 d's per thread. fp32.
// ============================================================
__global__ __launch_bounds__(256) void k_weff(
    const float* __restrict__ W1, const float* __restrict__ Wq, const float* __restrict__ Wk)
{
    __shared__ float w1s[K2];
    const int f = blockIdx.x;
    const int tid = threadIdx.x;
    for (int i = tid; i < K2; i += 256) w1s[i] = W1[(size_t)f * K2 + i];
    __syncthreads();

    const int d0 = tid * 3;
    float a0 = 0.f, a1 = 0.f, a2 = 0.f;
    #pragma unroll 4
    for (int e = 0; e < DIM; e++) {
        const float wa = w1s[e], wb = w1s[DIM + e];
        const float* qr = Wq + (size_t)e * DIM + d0;
        const float* kr = Wk + (size_t)e * DIM + d0;
        a0 = fmaf(wa, qr[0], fmaf(wb, kr[0], a0));
        a1 = fmaf(wa, qr[1], fmaf(wb, kr[1], a1));
        a2 = fmaf(wa, qr[2], fmaf(wb, kr[2], a2));
    }
    g_weff[(size_t)f * DIM + d0 + 0] = a0;
    g_weff[(size_t)f * DIM + d0 + 1] = a1;
    g_weff[(size_t)f * DIM + d0 + 2] = a2;
}

// beff[f] = b1[f] + sum_e W1[f][e]*bq[e] + W1[f][768+e]*bk[e]
__global__ void k_beff(const float* __restrict__ W1, const float* __restrict__ bq,
                       const float* __restrict__ bk, const float* __restrict__ b1)
{
    const int f = threadIdx.x;
    if (f < H60) {
        float s = b1[f];
        for (int e = 0; e < DIM; e++) {
            s = fmaf(W1[(size_t)f * K2 + e], bq[e], s);
            s = fmaf(W1[(size_t)f * K2 + DIM + e], bk[e], s);
        }
        g_beff[f] = s;
    }
}

// ============================================================
// TF32 GEMM (proven body): Q projection only.
// Block 128x128, K-step 32, 8 warps 2Mx4N. grid rt*6+ct, ct fastest.
// ============================================================
__global__ __launch_bounds__(256) void k_gemm_q_t(
    const float* __restrict__ X,
    const float* __restrict__ Wq, const float* __restrict__ bq)
{
    const int bx = blockIdx.x;
    const int rt = bx / 6;
    const int ct = bx - rt * 6;

    __shared__ __align__(16) uint32_t As[128][36];
    __shared__ __align__(16) uint32_t Bs[128][36];

    const int tid  = threadIdx.x;
    const int lane = tid & 31;
    const int wid  = tid >> 5;
    const int warpM = wid & 1;
    const int warpN = wid >> 1;

    const int row0 = rt * 128;
    const int col0 = ct * 128;

    const int ldr = tid >> 1;
    const int ldc = (tid & 1) * 16;

    const float* Ap = X + (size_t)(row0 + ldr) * DIM + ldc;
    const float* Bp = Wq + (size_t)(col0 + ldr) * DIM + ldc;

    const uint32_t As_addr = (uint32_t)__cvta_generic_to_shared(&As[0][0]);
    const uint32_t Bs_addr = (uint32_t)__cvta_generic_to_shared(&Bs[0][0]);
    const uint32_t a_base = As_addr + (((warpM*64 + (lane & 15)) * 36 + ((lane >> 4) << 2)) << 2);
    const uint32_t b_base = Bs_addr + (((warpN*32 + (lane & 15)) * 36 + ((lane >> 4) << 2)) << 2);

    float acc[4][4][4];
    #pragma unroll
    for (int mt = 0; mt < 4; mt++)
        #pragma unroll
        for (int nt = 0; nt < 4; nt++)
            #pragma unroll
            for (int i = 0; i < 4; i++) acc[mt][nt][i] = 0.f;

    float4 ra[4], rb[4];
    #pragma unroll
    for (int i = 0; i < 4; i++) {
        ra[i] = *reinterpret_cast<const float4*>(Ap + i*4);
        rb[i] = *reinterpret_cast<const float4*>(Bp + i*4);
    }

    for (int k0 = 0; k0 < DIM; k0 += 32) {
        #pragma unroll
        for (int i = 0; i < 4; i++) {
            uint4 ua = make_uint4(f2tf32(ra[i].x), f2tf32(ra[i].y), f2tf32(ra[i].z), f2tf32(ra[i].w));
            uint4 ub = make_uint4(f2tf32(rb[i].x), f2tf32(rb[i].y), f2tf32(rb[i].z), f2tf32(rb[i].w));
            *reinterpret_cast<uint4*>(&As[ldr][ldc + i*4]) = ua;
            *reinterpret_cast<uint4*>(&Bs[ldr][ldc + i*4]) = ub;
        }
        __syncthreads();
        if (k0 + 32 < DIM) {
            #pragma unroll
            for (int i = 0; i < 4; i++) {
                ra[i] = *reinterpret_cast<const float4*>(Ap + k0 + 32 + i*4);
                rb[i] = *reinterpret_cast<const float4*>(Bp + k0 + 32 + i*4);
            }
        }
        #pragma unroll
        for (int ks = 0; ks < 4; ks++) {
            uint32_t af[4][4], bf[4][2];
            #pragma unroll
            for (int mt = 0; mt < 4; mt++)
                ldsm_x4(af[mt][0], af[mt][1], af[mt][2], af[mt][3],
                        a_base + ((mt*16*36 + ks*8) << 2));
            #pragma unroll
            for (int nt2 = 0; nt2 < 2; nt2++) {
                uint32_t r0, r1, r2, r3;
                ldsm_x4(r0, r1, r2, r3, b_base + ((nt2*16*36 + ks*8) << 2));
                bf[2*nt2  ][0] = r0; bf[2*nt2+1][0] = r1;
                bf[2*nt2  ][1] = r2; bf[2*nt2+1][1] = r3;
            }
            #pragma unroll
            for (int mt = 0; mt < 4; mt++)
                #pragma unroll
                for (int nt = 0; nt < 4; nt++)
                    mma_tf32(acc[mt][nt], af[mt], bf[nt]);
        }
        __syncthreads();
    }

    #pragma unroll
    for (int nt = 0; nt < 4; nt++) {
        const int c = col0 + warpN*32 + nt*8 + 2*(lane & 3);
        const float b0v = bq[c];
        const float b1v = bq[c + 1];
        #pragma unroll
        for (int mt = 0; mt < 4; mt++) {
            const int r = row0 + warpM*64 + mt*16 + (lane >> 2);
            float2 o0 = make_float2(acc[mt][nt][0] + b0v, acc[mt][nt][1] + b1v);
            float2 o1 = make_float2(acc[mt][nt][2] + b0v, acc[mt][nt][3] + b1v);
            *reinterpret_cast<float2*>(g_q + (size_t)r * DIM + c)       = o0;
            *reinterpret_cast<float2*>(g_q + (size_t)(r + 8) * DIM + c) = o1;
        }
    }
}

// ============================================================
// TF32 K+V projections on the 64 reachable tokens per batch.
// grid = 128 * 12; rem = bx%12: ct = rem%6, zz = rem/6 (0=K, 1=V).
// ============================================================
__global__ __launch_bounds__(256) void k_gemm_kv_t(
    const float* __restrict__ X,
    const float* __restrict__ Wk, const float* __restrict__ bk,
    const float* __restrict__ Wv, const float* __restrict__ bv)
{
    __shared__ __align__(16) uint32_t As[128][36];
    __shared__ __align__(16) uint32_t Bs[128][36];

    const int bx  = blockIdx.x;
    const int rt  = bx / 12;
    const int rem = bx - rt * 12;
    const int ct  = rem % 6;
    const int zz  = rem / 6;

    const float* W    = zz ? Wv : Wk;
    const float* bias = zz ? bv : bk;
    float*       Y    = zz ? g_vs : g_kr;

    const int tid  = threadIdx.x;
    const int lane = tid & 31;
    const int wid  = tid >> 5;
    const int warpM = wid & 1;
    const int warpN = wid >> 1;

    const int row0 = rt * 128;
    const int col0 = ct * 128;

    const int ldr = tid >> 1;
    const int ldc = (tid & 1) * 16;

    const int r_g = row0 + ldr;
    const int bb  = r_g >> 6;
    const int jj  = r_g & 63;
    const int token = 1 + (6 + (jj >> 3)) * GRID + (6 + (jj & 7));
    const float* Ap = X + (size_t)(bb * SEQ + token) * DIM + ldc;
    const float* Bp = W + (size_t)(col0 + ldr) * DIM + ldc;

    const uint32_t As_addr = (uint32_t)__cvta_generic_to_shared(&As[0][0]);
    const uint32_t Bs_addr = (uint32_t)__cvta_generic_to_shared(&Bs[0][0]);
    const uint32_t a_base = As_addr + (((warpM*64 + (lane & 15)) * 36 + ((lane >> 4) << 2)) << 2);
    const uint32_t b_base = Bs_addr + (((warpN*32 + (lane & 15)) * 36 + ((lane >> 4) << 2)) << 2);

    float acc[4][4][4];
    #pragma unroll
    for (int mt = 0; mt < 4; mt++)
        #pragma unroll
        for (int nt = 0; nt < 4; nt++)
            #pragma unroll
            for (int i = 0; i < 4; i++) acc[mt][nt][i] = 0.f;

    float4 ra[4], rb[4];
    #pragma unroll
    for (int i = 0; i < 4; i++) {
        ra[i] = *reinterpret_cast<const float4*>(Ap + i*4);
        rb[i] = *reinterpret_cast<const float4*>(Bp + i*4);
    }

    for (int k0 = 0; k0 < DIM; k0 += 32) {
        #pragma unroll
        for (int i = 0; i < 4; i++) {
            uint4 ua = make_uint4(f2tf32(ra[i].x), f2tf32(ra[i].y), f2tf32(ra[i].z), f2tf32(ra[i].w));
            uint4 ub = make_uint4(f2tf32(rb[i].x), f2tf32(rb[i].y), f2tf32(rb[i].z), f2tf32(rb[i].w));
            *reinterpret_cast<uint4*>(&As[ldr][ldc + i*4]) = ua;
            *reinterpret_cast<uint4*>(&Bs[ldr][ldc + i*4]) = ub;
        }
        __syncthreads();
        if (k0 + 32 < DIM) {
            #pragma unroll
            for (int i = 0; i < 4; i++) {
                ra[i] = *reinterpret_cast<const float4*>(Ap + k0 + 32 + i*4);
                rb[i] = *reinterpret_cast<const float4*>(Bp + k0 + 32 + i*4);
            }
        }
        #pragma unroll
        for (int ks = 0; ks < 4; ks++) {
            uint32_t af[4][4], bf[4][2];
            #pragma unroll
            for (int mt = 0; mt < 4; mt++)
                ldsm_x4(af[mt][0], af[mt][1], af[mt][2], af[mt][3],
                        a_base + ((mt*16*36 + ks*8) << 2));
            #pragma unroll
            for (int nt2 = 0; nt2 < 2; nt2++) {
                uint32_t r0, r1, r2, r3;
                ldsm_x4(r0, r1, r2, r3, b_base + ((nt2*16*36 + ks*8) << 2));
                bf[2*nt2  ][0] = r0; bf[2*nt2+1][0] = r1;
                bf[2*nt2  ][1] = r2; bf[2*nt2+1][1] = r3;
            }
            #pragma unroll
            for (int mt = 0; mt < 4; mt++)
                #pragma unroll
                for (int nt = 0; nt < 4; nt++)
                    mma_tf32(acc[mt][nt], af[mt], bf[nt]);
        }
        __syncthreads();
    }

    #pragma unroll
    for (int nt = 0; nt < 4; nt++) {
        const int c = col0 + warpN*32 + nt*8 + 2*(lane & 3);
        const float b0v = bias[c];
        const float b1v = bias[c + 1];
        #pragma unroll
        for (int mt = 0; mt < 4; mt++) {
            const int r = row0 + warpM*64 + mt*16 + (lane >> 2);
            float2 o0 = make_float2(acc[mt][nt][0] + b0v, acc[mt][nt][1] + b1v);
            float2 o1 = make_float2(acc[mt][nt][2] + b0v, acc[mt][nt][3] + b1v);
            *reinterpret_cast<float2*>(Y + (size_t)r * DIM + c)       = o0;
            *reinterpret_cast<float2*>(Y + (size_t)(r + 8) * DIM + c) = o1;
        }
    }
}

// ============================================================
// TF32 fused MLP layer 1: h1 = relu(X @ Weff^T + beff). K=768.
// Block 128x64; 8 warps 4Mx2N.
// ============================================================
__global__ __launch_bounds__(256) void k_gemm_h1_t()
{
    __shared__ __align__(16) uint32_t As[128][36];
    __shared__ __align__(16) uint32_t Bs[64][36];

    const int tid  = threadIdx.x;
    const int lane = tid & 31;
    const int wid  = tid >> 5;
    const int warpM = wid & 3;
    const int warpN = wid >> 2;

    const int row0 = blockIdx.x * 128;

    const int ldr = tid >> 1;
    const int ldc = (tid & 1) * 16;

    const int r_g = row0 + ldr;
    const int bb  = r_g / SN;
    const int tt  = r_g - bb * SN;
    const size_t aoff = (size_t)(bb * SEQ + tt + 1) * DIM + ldc;

    const int ldr2 = tid >> 2;
    const int ldc2 = (tid & 3) * 8;
    const bool bvalid = (ldr2 < H60);
    const float* Bp = g_weff + (size_t)ldr2 * DIM + ldc2;

    const uint32_t As_addr = (uint32_t)__cvta_generic_to_shared(&As[0][0]);
    const uint32_t Bs_addr = (uint32_t)__cvta_generic_to_shared(&Bs[0][0]);
    const uint32_t a_base = As_addr + (((warpM*32 + (lane & 15)) * 36 + ((lane >> 4) << 2)) << 2);
    const uint32_t b_base = Bs_addr + (((warpN*32 + (lane & 15)) * 36 + ((lane >> 4) << 2)) << 2);

    float acc[2][4][4];
    #pragma unroll
    for (int mt = 0; mt < 2; mt++)
        #pragma unroll
        for (int nt = 0; nt < 4; nt++)
            #pragma unroll
            for (int i = 0; i < 4; i++) acc[mt][nt][i] = 0.f;

    extern __shared__ char dummy[];
    const float* Xa = nullptr;   // placeholder to keep structure; A comes from x passed via const mem? no:
    // A source is the harness input X; pass via global pointer:
    // (handled through kernel parameter below)
    (void)Xa; (void)dummy;
    // NOTE: parameters are added in the wrapper declaration
    asm volatile("" ::: "memory");
    // This kernel body continues in k_gemm_h1_t_impl pattern below.
}

// Re-declare properly with X parameter (the above stub is unused).
__global__ __launch_bounds__(256) void k_gemm_h1_x(const float* __restrict__ X)
{
    __shared__ __align__(16) uint32_t As[128][36];
    __shared__ __align__(16) uint32_t Bs[64][36];

    const int tid  = threadIdx.x;
    const int lane = tid & 31;
    const int wid  = tid >> 5;
    const int warpM = wid & 3;
    const int warpN = wid >> 2;

    const int row0 = blockIdx.x * 128;

    const int ldr = tid >> 1;
    const int ldc = (tid & 1) * 16;

    const int r_g = row0 + ldr;
    const int bb  = r_g / SN;
    const int tt  = r_g - bb * SN;
    const size_t aoff = (size_t)(bb * SEQ + tt + 1) * DIM + ldc;

    const int ldr2 = tid >> 2;
    const int ldc2 = (tid & 3) * 8;
    const bool bvalid = (ldr2 < H60);
    const float* Bp = g_weff + (size_t)ldr2 * DIM + ldc2;

    const uint32_t As_addr = (uint32_t)__cvta_generic_to_shared(&As[0][0]);
    const uint32_t Bs_addr = (uint32_t)__cvta_generic_to_shared(&Bs[0][0]);
    const uint32_t a_base = As_addr + (((warpM*32 + (lane & 15)) * 36 + ((lane >> 4) << 2)) << 2);
    const uint32_t b_base = Bs_addr + (((warpN*32 + (lane & 15)) * 36 + ((lane >> 4) << 2)) << 2);

    float acc[2][4][4];
    #pragma unroll
    for (int mt = 0; mt < 2; mt++)
        #pragma unroll
        for (int nt = 0; nt < 4; nt++)
            #pragma unroll
            for (int i = 0; i < 4; i++) acc[mt][nt][i] = 0.f;

    float4 ra[4], rb[2];
    {
        const float* base = X + aoff;
        #pragma unroll
        for (int i = 0; i < 4; i++)
            ra[i] = *reinterpret_cast<const float4*>(base + i*4);
        #pragma unroll
        for (int i = 0; i < 2; i++)
            rb[i] = bvalid ? *reinterpret_cast<const float4*>(Bp + i*4)
                           : make_float4(0.f, 0.f, 0.f, 0.f);
    }

    for (int k0 = 0; k0 < DIM; k0 += 32) {
        #pragma unroll
        for (int i = 0; i < 4; i++) {
            uint4 ua = make_uint4(f2tf32(ra[i].x), f2tf32(ra[i].y), f2tf32(ra[i].z), f2tf32(ra[i].w));
            *reinterpret_cast<uint4*>(&As[ldr][ldc + i*4]) = ua;
        }
        #pragma unroll
        for (int i = 0; i < 2; i++) {
            uint4 ub = make_uint4(f2tf32(rb[i].x), f2tf32(rb[i].y), f2tf32(rb[i].z), f2tf32(rb[i].w));
            *reinterpret_cast<uint4*>(&Bs[ldr2][ldc2 + i*4]) = ub;
        }
        __syncthreads();
        if (k0 + 32 < DIM) {
            const int kn = k0 + 32;
            const float* base = X + aoff + kn;
            #pragma unroll
            for (int i = 0; i < 4; i++)
                ra[i] = *reinterpret_cast<const float4*>(base + i*4);
            #pragma unroll
            for (int i = 0; i < 2; i++)
                rb[i] = bvalid ? *reinterpret_cast<const float4*>(Bp + kn + i*4)
                               : make_float4(0.f, 0.f, 0.f, 0.f);
        }
        #pragma unroll
        for (int ks = 0; ks < 4; ks++) {
            uint32_t af[2][4], bf[4][2];
            #pragma unroll
            for (int mt = 0; mt < 2; mt++)
                ldsm_x4(af[mt][0], af[mt][1], af[mt][2], af[mt][3],
                        a_base + ((mt*16*36 + ks*8) << 2));
            #pragma unroll
            for (int nt2 = 0; nt2 < 2; nt2++) {
                uint32_t r0, r1, r2, r3;
                ldsm_x4(r0, r1, r2, r3, b_base + ((nt2*16*36 + ks*8) << 2));
                bf[2*nt2  ][0] = r0; bf[2*nt2+1][0] = r1;
                bf[2*nt2  ][1] = r2; bf[2*nt2+1][1] = r3;
            }
            #pragma unroll
            for (int mt = 0; mt < 2; mt++)
                #pragma unroll
                for (int nt = 0; nt < 4; nt++)
                    mma_tf32(acc[mt][nt], af[mt], bf[nt]);
        }
        __syncthreads();
    }

    #pragma unroll
    for (int nt = 0; nt < 4; nt++) {
        const int c = warpN*32 + nt*8 + 2*(lane & 3);
        const float b0v = (c     < H60) ? g_beff[c]     : 0.f;
        const float b1v = (c + 1 < H60) ? g_beff[c + 1] : 0.f;
        #pragma unroll
        for (int mt = 0; mt < 2; mt++) {
            const int r = row0 + warpM*32 + mt*16 + (lane >> 2);
            if (c < H60) {
                g_h1[(size_t)r * H60 + c]       = fmaxf(acc[mt][nt][0] + b0v, 0.f);
                g_h1[(size_t)(r + 8) * H60 + c] = fmaxf(acc[mt][nt][2] + b0v, 0.f);
            }
            if (c + 1 < H60) {
                g_h1[(size_t)r * H60 + c + 1]       = fmaxf(acc[mt][nt][1] + b1v, 0.f);
                g_h1[(size_t)(r + 8) * H60 + c + 1] = fmaxf(acc[mt][nt][3] + b1v, 0.f);
            }
        }
    }
}

// ============================================================
// MLP layers 2+3 (unchanged)
// ============================================================
__global__ __launch_bounds__(256) void k_mlp23(
    const float* __restrict__ W2, const float* __restrict__ b2,
    const float* __restrict__ W3, const float* __restrict__ b3)
{
    __shared__ float W2s[60*61], W3s[120], b2s[60], b3s[2], h1s[16][60], h2s[16][60];
    const int tid = threadIdx.x;
    for (int i = tid; i < 3600; i += 256) { int rr = i / 60, cc = i - rr * 60; W2s[rr*61+cc] = W2[i]; }
    if (tid < 120) W3s[tid] = W3[tid];
    if (tid < 60)  b2s[tid] = b2[tid];
    if (tid < 2)   b3s[tid] = b3[tid];
    const int r0 = blockIdx.x * 16;
    for (int i = tid; i < 960; i += 256) { int t = i / 60, c = i - t * 60; h1s[t][c] = g_h1[(size_t)(r0+t)*H60 + c]; }
    __syncthreads();
    const int tg = tid >> 6, f = tid & 63;
    if (f < H60) {
        float a0 = b2s[f], a1 = a0, a2 = a0, a3 = a0;
        #pragma unroll 4
        for (int g = 0; g < H60; g++) {
            const float w = W2s[f*61 + g];
            a0 = fmaf(w, h1s[tg*4+0][g], a0); a1 = fmaf(w, h1s[tg*4+1][g], a1);
            a2 = fmaf(w, h1s[tg*4+2][g], a2); a3 = fmaf(w, h1s[tg*4+3][g], a3);
        }
        h2s[tg*4+0][f] = fmaxf(a0, 0.f); h2s[tg*4+1][f] = fmaxf(a1, 0.f);
        h2s[tg*4+2][f] = fmaxf(a2, 0.f); h2s[tg*4+3][f] = fmaxf(a3, 0.f);
    }
    __syncthreads();
    if (tid < 32) {
        int t2 = tid >> 1, c = tid & 1;
        float s = b3s[c];
        #pragma unroll 4
        for (int g = 0; g < H60; g++) s = fmaf(W3s[c*60+g], h2s[t2][g], s);
        g_sample[(size_t)(r0+t2)*2 + c] = 1.f / (1.f + expf(-s));
    }
}

// ============================================================
// Grid coordinate shuffle + unnormalize (unchanged)
// ============================================================
__global__ void k_coords()
{
    const int id = blockIdx.x * 256 + threadIdx.x;
    const int b = id / SN, p = id - b * SN;
    const int q1 = 2 * p, q2 = 2 * p + 1;
    float gx = (q1 < SN) ? g_sample[(size_t)(b*SN+q1)*2+0] : g_sample[(size_t)(b*SN+q1-SN)*2+1];
    float gy = (q2 < SN) ? g_sample[(size_t)(b*SN+q2)*2+0] : g_sample[(size_t)(b*SN+q2-SN)*2+1];
    g_coords[(size_t)id*2+0] = ((gx + 1.f) * (float)GRID - 1.f) * 0.5f;
    g_coords[(size_t)id*2+1] = ((gy + 1.f) * (float)GRID - 1.f) * 0.5f;
}

// ============================================================
// Epilogue (round-15 float4 version): 192 threads per (b,s) row.
// k and v both gathered from reachable-token arrays (same rows).
// ============================================================
__global__ __launch_bounds__(192) void k_epilogue(float* __restrict__ out)
{
    const int bs = blockIdx.x;
    const int b  = bs / SEQ;
    const int s  = bs - b * SEQ;
    const int tid = threadIdx.x;
    const int lane = tid & 31;
    const int wid  = tid >> 5;
    __shared__ float red[6];
    __shared__ float sigsh;

    const size_t qbase = (size_t)bs * DIM;
    const int d0 = tid * 4;

    float  w[4];
    size_t roww[4];
    bool   vv[4];

    if (s > 0) {
        const int p = s - 1;
        const float ix = g_coords[(size_t)(b*SN + p)*2 + 0];
        const float iy = g_coords[(size_t)(b*SN + p)*2 + 1];
        const float ix0f = floorf(ix), iy0f = floorf(iy);
        const float wx1 = ix - ix0f, wx0 = 1.f - wx1;
        const float wy1 = iy - iy0f, wy0 = 1.f - wy1;
        const int x0 = (int)ix0f, y0 = (int)iy0f;
        const int xs[4] = {x0, x0+1, x0, x0+1};
        const int ys[4] = {y0, y0, y0+1, y0+1};
        const float ws[4] = {wy0*wx0, wy0*wx1, wy1*wx0, wy1*wx1};
        #pragma unroll
        for (int c = 0; c < 4; c++) {
            const int x = xs[c], y = ys[c];
            const bool v2 = (x >= 6) && (x <= 13) && (y >= 6) && (y <= 13);
            vv[c] = v2; w[c] = ws[c];
            roww[c] = v2 ? (size_t)(b * 64 + (y-6)*8 + (x-6)) * DIM : 0;
        }
    }

    float4 sk4, sv4;
    if (s == 0) {
        sk4 = make_float4(1.f, 1.f, 1.f, 1.f);
        sv4 = make_float4(1.f, 1.f, 1.f, 1.f);
    } else {
        sk4 = make_float4(0.f, 0.f, 0.f, 0.f);
        sv4 = make_float4(0.f, 0.f, 0.f, 0.f);
        #pragma unroll
        for (int c = 0; c < 4; c++) {
            if (vv[c]) {
                const float4 kv = *reinterpret_cast<const float4*>(g_kr + roww[c] + d0);
                const float4 vf = *reinterpret_cast<const float4*>(g_vs + roww[c] + d0);
                sk4.x = fmaf(w[c], kv.x, sk4.x); sk4.y = fmaf(w[c], kv.y, sk4.y);
                sk4.z = fmaf(w[c], kv.z, sk4.z); sk4.w = fmaf(w[c], kv.w, sk4.w);
                sv4.x = fmaf(w[c], vf.x, sv4.x); sv4.y = fmaf(w[c], vf.y, sv4.y);
                sv4.z = fmaf(w[c], vf.z, sv4.z); sv4.w = fmaf(w[c], vf.w, sv4.w);
            }
        }
    }

    const float4 q4 = *reinterpret_cast<const float4*>(g_q + qbase + d0);
    float part = fmaf(sk4.x, q4.x, fmaf(sk4.y, q4.y, fmaf(sk4.z, q4.z, sk4.w * q4.w)));

    #pragma unroll
    for (int off = 16; off > 0; off >>= 1)
        part += __shfl_xor_sync(0xffffffffu, part, off);
    if (lane == 0) red[wid] = part;
    __syncthreads();
    if (tid == 0) {
        float sum = red[0] + red[1] + red[2] + red[3] + red[4] + red[5];
        sigsh = 1.f / (1.f + expf(-0.01f * sum));
    }
    __syncthreads();
    const float sg = sigsh;
    float4 o = make_float4(sg * sv4.x, sg * sv4.y, sg * sv4.z, sg * sv4.w);
    *reinterpret_cast<float4*>(out + qbase + d0) = o;
}

// ============================================================
extern "C" void kernel_launch(void* const* d_in, const int* in_sizes, int n_in,
                              void* d_out, int out_size)
{
    const float* x  = (const float*)d_in[0];
    const float* Wq = (const float*)d_in[2];  const float* bq = (const float*)d_in[3];
    const float* Wk = (const float*)d_in[4];  const float* bk = (const float*)d_in[5];
    const float* Wv = (const float*)d_in[6];  const float* bv = (const float*)d_in[7];
    const float* W1 = (const float*)d_in[8];  const float* b1 = (const float*)d_in[9];
    const float* W2 = (const float*)d_in[10]; const float* b2 = (const float*)d_in[11];
    const float* W3 = (const float*)d_in[12]; const float* b3 = (const float*)d_in[13];
    float* out = (float*)d_out;

    // folded MLP-layer-1 weights: Weff = W1q@Wq + W1k@Wk, beff = b1 + W1q.bq + W1k.bk
    k_weff<<<60, 256>>>(W1, Wq, Wk);
    k_beff<<<1, 64>>>(W1, bq, bk, b1);
    // Q projection (full 50432 rows)
    k_gemm_q_t<<<394 * 6, 256>>>(x, Wq, bq);
    // K,V projections on the 64 reachable tokens/batch
    k_gemm_kv_t<<<128 * 12, 256>>>(x, Wk, bk, Wv, bv);
    // fused MLP layer 1 from X (K=768)
    k_gemm_h1_x<<<392, 256>>>(x);
    // MLP layers 2+3 -> sample
    k_mlp23<<<3136, 256>>>(W2, b2, W3, b3);
    // coords
    k_coords<<<196, 256>>>();
    // gather + scores + output
    k_epilogue<<<MQK, 192>>>(out);
}

// round 17
// speedup vs baseline: 2.4932x; 1.3091x over previous
#include <cuda_runtime.h>
#include <cstdint>

#define BATCH 256
#define SEQ   197
#define SN    196
#define DIM   768
#define GRID  14
#define MQK   (BATCH*SEQ)
#define MH    (BATCH*SN)
#define MV    (BATCH*64)
#define H60   60
#define K2    1536

__device__ float g_y  [(size_t)MV  * DIM];   // y_t = G x_t, reachable tokens
__device__ float g_vs [(size_t)MV  * DIM];
__device__ float g_h1 [(size_t)MH  * H60];
__device__ float g_sample[(size_t)MH * 2];
__device__ float g_coords[(size_t)MH * 2];
__device__ float g_weff[(size_t)H60 * DIM];
__device__ float g_beff[H60];
__device__ float g_gmat[(size_t)DIM * DIM];  // G = Wq^T Wk, row-major [d1][d2]
__device__ float g_u [DIM];                  // Wq^T bk
__device__ float g_v [DIM];                  // Wk^T bq
__device__ float g_cq[DIM];                  // colsum(Wq)
__device__ float g_z [MV];                   // z_t = x_t . v
__device__ float g_sc[2];                    // {c0 = bq.bk, sb = sum(bq)}
__device__ float g_zero[DIM];                // stays zero (module init)

__device__ __forceinline__ uint32_t f2tf32(float f) {
    uint32_t u;
    asm("cvt.rna.tf32.f32 %0, %1;" : "=r"(u) : "f"(f));
    return u;
}

__device__ __forceinline__ void mma_tf32(float (&d)[4], const uint32_t (&a)[4], const uint32_t (&b)[2]) {
    asm volatile(
        "mma.sync.aligned.m16n8k8.row.col.f32.tf32.tf32.f32 "
        "{%0,%1,%2,%3}, {%4,%5,%6,%7}, {%8,%9}, {%0,%1,%2,%3};\n"
        : "+f"(d[0]), "+f"(d[1]), "+f"(d[2]), "+f"(d[3])
        : "r"(a[0]), "r"(a[1]), "r"(a[2]), "r"(a[3]), "r"(b[0]), "r"(b[1]));
}

__device__ __forceinline__ void ldsm_x4(uint32_t& r0, uint32_t& r1, uint32_t& r2, uint32_t& r3, uint32_t addr) {
    asm volatile("ldmatrix.sync.aligned.m8n8.x4.shared.b16 {%0,%1,%2,%3}, [%4];"
                 : "=r"(r0), "=r"(r1), "=r"(r2), "=r"(r3) : "r"(addr));
}

// ============================================================
// Weff[f][d] = sum_e W1[f][e]*Wq[e][d] + W1[f][768+e]*Wk[e][d]  (fp32)
// ============================================================
__global__ __launch_bounds__(256) void k_weff(
    const float* __restrict__ W1, const float* __restrict__ Wq, const float* __restrict__ Wk)
{
    __shared__ float w1s[K2];
    const int f = blockIdx.x;
    const int tid = threadIdx.x;
    for (int i = tid; i < K2; i += 256) w1s[i] = W1[(size_t)f * K2 + i];
    __syncthreads();

    const int d0 = tid * 3;
    float a0 = 0.f, a1 = 0.f, a2 = 0.f;
    #pragma unroll 4
    for (int e = 0; e < DIM; e++) {
        const float wa = w1s[e], wb = w1s[DIM + e];
        const float* qr = Wq + (size_t)e * DIM + d0;
        const float* kr = Wk + (size_t)e * DIM + d0;
        a0 = fmaf(wa, qr[0], fmaf(wb, kr[0], a0));
        a1 = fmaf(wa, qr[1], fmaf(wb, kr[1], a1));
        a2 = fmaf(wa, qr[2], fmaf(wb, kr[2], a2));
    }
    g_weff[(size_t)f * DIM + d0 + 0] = a0;
    g_weff[(size_t)f * DIM + d0 + 1] = a1;
    g_weff[(size_t)f * DIM + d0 + 2] = a2;
}

__global__ void k_beff(const float* __restrict__ W1, const float* __restrict__ bq,
                       const float* __restrict__ bk, const float* __restrict__ b1)
{
    const int f = threadIdx.x;
    if (f < H60) {
        float s = b1[f];
        for (int e = 0; e < DIM; e++) {
            s = fmaf(W1[(size_t)f * K2 + e], bq[e], s);
            s = fmaf(W1[(size_t)f * K2 + DIM + e], bk[e], s);
        }
        g_beff[f] = s;
    }
}

// ============================================================
// G[d1][d2] = sum_e Wq[e][d1] * Wk[e][d2]  (fp32 tiled, 64x64 tiles)
// grid 144 = 12x12; 256 threads; 4x4 outputs per thread; K-chunk 16.
// ============================================================
__global__ __launch_bounds__(256) void k_gmat(
    const float* __restrict__ Wq, const float* __restrict__ Wk)
{
    __shared__ __align__(16) float Aq[16][68];
    __shared__ __align__(16) float Ak[16][68];

    const int tid = threadIdx.x;
    const int bt1 = blockIdx.x / 12, bt2 = blockIdx.x - bt1 * 12;
    const int d1_0 = bt1 * 64, d2_0 = bt2 * 64;

    const int lr = tid >> 4;          // 0..15 (e within chunk)
    const int lc = (tid & 15) * 4;    // 0..60

    const int ty = tid >> 4;          // 0..15 -> 4 d1's
    const int tx = tid & 15;          // 0..15 -> 4 d2's

    float acc[4][4];
    #pragma unroll
    for (int i = 0; i < 4; i++)
        #pragma unroll
        for (int j = 0; j < 4; j++) acc[i][j] = 0.f;

    for (int e0 = 0; e0 < DIM; e0 += 16) {
        *reinterpret_cast<float4*>(&Aq[lr][lc]) =
            *reinterpret_cast<const float4*>(Wq + (size_t)(e0 + lr) * DIM + d1_0 + lc);
        *reinterpret_cast<float4*>(&Ak[lr][lc]) =
            *reinterpret_cast<const float4*>(Wk + (size_t)(e0 + lr) * DIM + d2_0 + lc);
        __syncthreads();
        #pragma unroll
        for (int e = 0; e < 16; e++) {
            float4 a = *reinterpret_cast<const float4*>(&Aq[e][ty*4]);
            float4 b = *reinterpret_cast<const float4*>(&Ak[e][tx*4]);
            float av[4] = {a.x, a.y, a.z, a.w};
            float bv[4] = {b.x, b.y, b.z, b.w};
            #pragma unroll
            for (int i = 0; i < 4; i++)
                #pragma unroll
                for (int j = 0; j < 4; j++)
                    acc[i][j] = fmaf(av[i], bv[j], acc[i][j]);
        }
        __syncthreads();
    }

    #pragma unroll
    for (int i = 0; i < 4; i++) {
        float4 o = make_float4(acc[i][0], acc[i][1], acc[i][2], acc[i][3]);
        *reinterpret_cast<float4*>(g_gmat + (size_t)(d1_0 + ty*4 + i) * DIM + d2_0 + tx*4) = o;
    }
}

// u[d] = Wq^T bk, v[d] = Wk^T bq, cq[d] = colsum(Wq). grid 3, block 256.
__global__ __launch_bounds__(256) void k_vec(
    const float* __restrict__ Wq, const float* __restrict__ Wk,
    const float* __restrict__ bq, const float* __restrict__ bk)
{
    const int d = blockIdx.x * 256 + threadIdx.x;
    float su = 0.f, sv = 0.f, sc = 0.f;
    for (int e = 0; e < DIM; e++) {
        const float wq = Wq[(size_t)e * DIM + d];
        const float wk = Wk[(size_t)e * DIM + d];
        su = fmaf(wq, bk[e], su);
        sv = fmaf(wk, bq[e], sv);
        sc += wq;
    }
    g_u[d] = su; g_v[d] = sv; g_cq[d] = sc;
}

// c0 = bq.bk, sb = sum(bq). one warp.
__global__ void k_scal(const float* __restrict__ bq, const float* __restrict__ bk)
{
    const int lane = threadIdx.x;
    float c0 = 0.f, sb = 0.f;
    for (int e = lane; e < DIM; e += 32) {
        c0 = fmaf(bq[e], bk[e], c0);
        sb += bq[e];
    }
    #pragma unroll
    for (int off = 16; off > 0; off >>= 1) {
        c0 += __shfl_xor_sync(0xffffffffu, c0, off);
        sb += __shfl_xor_sync(0xffffffffu, sb, off);
    }
    if (lane == 0) { g_sc[0] = c0; g_sc[1] = sb; }
}

// z_t = x_t . v over the 16384 reachable tokens. warp per token.
__global__ __launch_bounds__(256) void k_z(const float* __restrict__ X)
{
    const int t = blockIdx.x * 8 + (threadIdx.x >> 5);
    const int lane = threadIdx.x & 31;
    const int b = t >> 6, j = t & 63;
    const int token = 1 + (6 + (j >> 3)) * GRID + (6 + (j & 7));
    const float* xr = X + (size_t)(b * SEQ + token) * DIM;
    float s = 0.f;
    #pragma unroll 6
    for (int d = lane; d < DIM; d += 32) s = fmaf(xr[d], g_v[d], s);
    #pragma unroll
    for (int off = 16; off > 0; off >>= 1) s += __shfl_xor_sync(0xffffffffu, s, off);
    if (lane == 0) g_z[t] = s;
}

// ============================================================
// TF32 GEMM on the 64 reachable tokens/batch: y (B=G) and V (B=Wv).
// grid = 128 * 12; rem: ct = rem%6, zz = rem/6 (0=y, 1=V).
// ============================================================
__global__ __launch_bounds__(256) void k_gemm_yv_t(
    const float* __restrict__ X,
    const float* __restrict__ Wv, const float* __restrict__ bv)
{
    __shared__ __align__(16) uint32_t As[128][36];
    __shared__ __align__(16) uint32_t Bs[128][36];

    const int bx  = blockIdx.x;
    const int rt  = bx / 12;
    const int rem = bx - rt * 12;
    const int ct  = rem % 6;
    const int zz  = rem / 6;

    const float* W    = zz ? Wv : g_gmat;
    const float* bias = zz ? bv : g_zero;
    float*       Y    = zz ? g_vs : g_y;

    const int tid  = threadIdx.x;
    const int lane = tid & 31;
    const int wid  = tid >> 5;
    const int warpM = wid & 1;
    const int warpN = wid >> 1;

    const int row0 = rt * 128;
    const int col0 = ct * 128;

    const int ldr = tid >> 1;
    const int ldc = (tid & 1) * 16;

    const int r_g = row0 + ldr;
    const int bb  = r_g >> 6;
    const int jj  = r_g & 63;
    const int token = 1 + (6 + (jj >> 3)) * GRID + (6 + (jj & 7));
    const float* Ap = X + (size_t)(bb * SEQ + token) * DIM + ldc;
    // y: Y[t][d1] = sum_d2 G[d1][d2] x_t[d2]  -> B row d1 = G row (K-major over d2). OK.
    const float* Bp = W + (size_t)(col0 + ldr) * DIM + ldc;

    const uint32_t As_addr = (uint32_t)__cvta_generic_to_shared(&As[0][0]);
    const uint32_t Bs_addr = (uint32_t)__cvta_generic_to_shared(&Bs[0][0]);
    const uint32_t a_base = As_addr + (((warpM*64 + (lane & 15)) * 36 + ((lane >> 4) << 2)) << 2);
    const uint32_t b_base = Bs_addr + (((warpN*32 + (lane & 15)) * 36 + ((lane >> 4) << 2)) << 2);

    float acc[4][4][4];
    #pragma unroll
    for (int mt = 0; mt < 4; mt++)
        #pragma unroll
        for (int nt = 0; nt < 4; nt++)
            #pragma unroll
            for (int i = 0; i < 4; i++) acc[mt][nt][i] = 0.f;

    float4 ra[4], rb[4];
    #pragma unroll
    for (int i = 0; i < 4; i++) {
        ra[i] = *reinterpret_cast<const float4*>(Ap + i*4);
        rb[i] = *reinterpret_cast<const float4*>(Bp + i*4);
    }

    for (int k0 = 0; k0 < DIM; k0 += 32) {
        #pragma unroll
        for (int i = 0; i < 4; i++) {
            uint4 ua = make_uint4(f2tf32(ra[i].x), f2tf32(ra[i].y), f2tf32(ra[i].z), f2tf32(ra[i].w));
            uint4 ub = make_uint4(f2tf32(rb[i].x), f2tf32(rb[i].y), f2tf32(rb[i].z), f2tf32(rb[i].w));
            *reinterpret_cast<uint4*>(&As[ldr][ldc + i*4]) = ua;
            *reinterpret_cast<uint4*>(&Bs[ldr][ldc + i*4]) = ub;
        }
        __syncthreads();
        if (k0 + 32 < DIM) {
            #pragma unroll
            for (int i = 0; i < 4; i++) {
                ra[i] = *reinterpret_cast<const float4*>(Ap + k0 + 32 + i*4);
                rb[i] = *reinterpret_cast<const float4*>(Bp + k0 + 32 + i*4);
            }
        }
        #pragma unroll
        for (int ks = 0; ks < 4; ks++) {
            uint32_t af[4][4], bf[4][2];
            #pragma unroll
            for (int mt = 0; mt < 4; mt++)
                ldsm_x4(af[mt][0], af[mt][1], af[mt][2], af[mt][3],
                        a_base + ((mt*16*36 + ks*8) << 2));
            #pragma unroll
            for (int nt2 = 0; nt2 < 2; nt2++) {
                uint32_t r0, r1, r2, r3;
                ldsm_x4(r0, r1, r2, r3, b_base + ((nt2*16*36 + ks*8) << 2));
                bf[2*nt2  ][0] = r0; bf[2*nt2+1][0] = r1;
                bf[2*nt2  ][1] = r2; bf[2*nt2+1][1] = r3;
            }
            #pragma unroll
            for (int mt = 0; mt < 4; mt++)
                #pragma unroll
                for (int nt = 0; nt < 4; nt++)
                    mma_tf32(acc[mt][nt], af[mt], bf[nt]);
        }
        __syncthreads();
    }

    #pragma unroll
    for (int nt = 0; nt < 4; nt++) {
        const int c = col0 + warpN*32 + nt*8 + 2*(lane & 3);
        const float b0v = bias[c];
        const float b1v = bias[c + 1];
        #pragma unroll
        for (int mt = 0; mt < 4; mt++) {
            const int r = row0 + warpM*64 + mt*16 + (lane >> 2);
            float2 o0 = make_float2(acc[mt][nt][0] + b0v, acc[mt][nt][1] + b1v);
            float2 o1 = make_float2(acc[mt][nt][2] + b0v, acc[mt][nt][3] + b1v);
            *reinterpret_cast<float2*>(Y + (size_t)r * DIM + c)       = o0;
            *reinterpret_cast<float2*>(Y + (size_t)(r + 8) * DIM + c) = o1;
        }
    }
}

// ============================================================
// TF32 fused MLP layer 1: h1 = relu(X @ Weff^T + beff). K=768.
// ============================================================
__global__ __launch_bounds__(256) void k_gemm_h1_x(const float* __restrict__ X)
{
    __shared__ __align__(16) uint32_t As[128][36];
    __shared__ __align__(16) uint32_t Bs[64][36];

    const int tid  = threadIdx.x;
    const int lane = tid & 31;
    const int wid  = tid >> 5;
    const int warpM = wid & 3;
    const int warpN = wid >> 2;

    const int row0 = blockIdx.x * 128;

    const int ldr = tid >> 1;
    const int ldc = (tid & 1) * 16;

    const int r_g = row0 + ldr;
    const int bb  = r_g / SN;
    const int tt  = r_g - bb * SN;
    const size_t aoff = (size_t)(bb * SEQ + tt + 1) * DIM + ldc;

    const int ldr2 = tid >> 2;
    const int ldc2 = (tid & 3) * 8;
    const bool bvalid = (ldr2 < H60);
    const float* Bp = g_weff + (size_t)ldr2 * DIM + ldc2;

    const uint32_t As_addr = (uint32_t)__cvta_generic_to_shared(&As[0][0]);
    const uint32_t Bs_addr = (uint32_t)__cvta_generic_to_shared(&Bs[0][0]);
    const uint32_t a_base = As_addr + (((warpM*32 + (lane & 15)) * 36 + ((lane >> 4) << 2)) << 2);
    const uint32_t b_base = Bs_addr + (((warpN*32 + (lane & 15)) * 36 + ((lane >> 4) << 2)) << 2);

    float acc[2][4][4];
    #pragma unroll
    for (int mt = 0; mt < 2; mt++)
        #pragma unroll
        for (int nt = 0; nt < 4; nt++)
            #pragma unroll
            for (int i = 0; i < 4; i++) acc[mt][nt][i] = 0.f;

    float4 ra[4], rb[2];
    {
        const float* base = X + aoff;
        #pragma unroll
        for (int i = 0; i < 4; i++)
            ra[i] = *reinterpret_cast<const float4*>(base + i*4);
        #pragma unroll
        for (int i = 0; i < 2; i++)
            rb[i] = bvalid ? *reinterpret_cast<const float4*>(Bp + i*4)
                           : make_float4(0.f, 0.f, 0.f, 0.f);
    }

    for (int k0 = 0; k0 < DIM; k0 += 32) {
        #pragma unroll
        for (int i = 0; i < 4; i++) {
            uint4 ua = make_uint4(f2tf32(ra[i].x), f2tf32(ra[i].y), f2tf32(ra[i].z), f2tf32(ra[i].w));
            *reinterpret_cast<uint4*>(&As[ldr][ldc + i*4]) = ua;
        }
        #pragma unroll
        for (int i = 0; i < 2; i++) {
            uint4 ub = make_uint4(f2tf32(rb[i].x), f2tf32(rb[i].y), f2tf32(rb[i].z), f2tf32(rb[i].w));
            *reinterpret_cast<uint4*>(&Bs[ldr2][ldc2 + i*4]) = ub;
        }
        __syncthreads();
        if (k0 + 32 < DIM) {
            const int kn = k0 + 32;
            const float* base = X + aoff + kn;
            #pragma unroll
            for (int i = 0; i < 4; i++)
                ra[i] = *reinterpret_cast<const float4*>(base + i*4);
            #pragma unroll
            for (int i = 0; i < 2; i++)
                rb[i] = bvalid ? *reinterpret_cast<const float4*>(Bp + kn + i*4)
                               : make_float4(0.f, 0.f, 0.f, 0.f);
        }
        #pragma unroll
        for (int ks = 0; ks < 4; ks++) {
            uint32_t af[2][4], bf[4][2];
            #pragma unroll
            for (int mt = 0; mt < 2; mt++)
                ldsm_x4(af[mt][0], af[mt][1], af[mt][2], af[mt][3],
                        a_base + ((mt*16*36 + ks*8) << 2));
            #pragma unroll
            for (int nt2 = 0; nt2 < 2; nt2++) {
                uint32_t r0, r1, r2, r3;
                ldsm_x4(r0, r1, r2, r3, b_base + ((nt2*16*36 + ks*8) << 2));
                bf[2*nt2  ][0] = r0; bf[2*nt2+1][0] = r1;
                bf[2*nt2  ][1] = r2; bf[2*nt2+1][1] = r3;
            }
            #pragma unroll
            for (int mt = 0; mt < 2; mt++)
                #pragma unroll
                for (int nt = 0; nt < 4; nt++)
                    mma_tf32(acc[mt][nt], af[mt], bf[nt]);
        }
        __syncthreads();
    }

    #pragma unroll
    for (int nt = 0; nt < 4; nt++) {
        const int c = warpN*32 + nt*8 + 2*(lane & 3);
        const float b0v = (c     < H60) ? g_beff[c]     : 0.f;
        const float b1v = (c + 1 < H60) ? g_beff[c + 1] : 0.f;
        #pragma unroll
        for (int mt = 0; mt < 2; mt++) {
            const int r = row0 + warpM*32 + mt*16 + (lane >> 2);
            if (c < H60) {
                g_h1[(size_t)r * H60 + c]       = fmaxf(acc[mt][nt][0] + b0v, 0.f);
                g_h1[(size_t)(r + 8) * H60 + c] = fmaxf(acc[mt][nt][2] + b0v, 0.f);
            }
            if (c + 1 < H60) {
                g_h1[(size_t)r * H60 + c + 1]       = fmaxf(acc[mt][nt][1] + b1v, 0.f);
                g_h1[(size_t)(r + 8) * H60 + c + 1] = fmaxf(acc[mt][nt][3] + b1v, 0.f);
            }
        }
    }
}

// ============================================================
// MLP layers 2+3 (unchanged)
// ============================================================
__global__ __launch_bounds__(256) void k_mlp23(
    const float* __restrict__ W2, const float* __restrict__ b2,
    const float* __restrict__ W3, const float* __restrict__ b3)
{
    __shared__ float W2s[60*61], W3s[120], b2s[60], b3s[2], h1s[16][60], h2s[16][60];
    const int tid = threadIdx.x;
    for (int i = tid; i < 3600; i += 256) { int rr = i / 60, cc = i - rr * 60; W2s[rr*61+cc] = W2[i]; }
    if (tid < 120) W3s[tid] = W3[tid];
    if (tid < 60)  b2s[tid] = b2[tid];
    if (tid < 2)   b3s[tid] = b3[tid];
    const int r0 = blockIdx.x * 16;
    for (int i = tid; i < 960; i += 256) { int t = i / 60, c = i - t * 60; h1s[t][c] = g_h1[(size_t)(r0+t)*H60 + c]; }
    __syncthreads();
    const int tg = tid >> 6, f = tid & 63;
    if (f < H60) {
        float a0 = b2s[f], a1 = a0, a2 = a0, a3 = a0;
        #pragma unroll 4
        for (int g = 0; g < H60; g++) {
            const float w = W2s[f*61 + g];
            a0 = fmaf(w, h1s[tg*4+0][g], a0); a1 = fmaf(w, h1s[tg*4+1][g], a1);
            a2 = fmaf(w, h1s[tg*4+2][g], a2); a3 = fmaf(w, h1s[tg*4+3][g], a3);
        }
        h2s[tg*4+0][f] = fmaxf(a0, 0.f); h2s[tg*4+1][f] = fmaxf(a1, 0.f);
        h2s[tg*4+2][f] = fmaxf(a2, 0.f); h2s[tg*4+3][f] = fmaxf(a3, 0.f);
    }
    __syncthreads();
    if (tid < 32) {
        int t2 = tid >> 1, c = tid & 1;
        float s = b3s[c];
        #pragma unroll 4
        for (int g = 0; g < H60; g++) s = fmaf(W3s[c*60+g], h2s[t2][g], s);
        g_sample[(size_t)(r0+t2)*2 + c] = 1.f / (1.f + expf(-s));
    }
}

__global__ void k_coords()
{
    const int id = blockIdx.x * 256 + threadIdx.x;
    const int b = id / SN, p = id - b * SN;
    const int q1 = 2 * p, q2 = 2 * p + 1;
    float gx = (q1 < SN) ? g_sample[(size_t)(b*SN+q1)*2+0] : g_sample[(size_t)(b*SN+q1-SN)*2+1];
    float gy = (q2 < SN) ? g_sample[(size_t)(b*SN+q2)*2+0] : g_sample[(size_t)(b*SN+q2-SN)*2+1];
    g_coords[(size_t)id*2+0] = ((gx + 1.f) * (float)GRID - 1.f) * 0.5f;
    g_coords[(size_t)id*2+1] = ((gy + 1.f) * (float)GRID - 1.f) * 0.5f;
}

// ============================================================
// Epilogue: 192 threads per (b,s). score via x_s and y/z (Q eliminated).
// s=0: score = x.cq + sb, sv = 1.
// s>0: score = x.(sum w_c y_c + W u) + sum w_c z_c + W c0; sv bilinear.
// ============================================================
__global__ __launch_bounds__(192) void k_epilogue(const float* __restrict__ X, float* __restrict__ out)
{
    const int bs = blockIdx.x;
    const int b  = bs / SEQ;
    const int s  = bs - b * SEQ;
    const int tid = threadIdx.x;
    const int lane = tid & 31;
    const int wid  = tid >> 5;
    __shared__ float red[6];
    __shared__ float sigsh;

    const size_t rbase = (size_t)bs * DIM;
    const int d0 = tid * 4;
    const float4 x4 = *reinterpret_cast<const float4*>(X + rbase + d0);

    float  w[4];
    size_t roww[4];
    int    tok[4];
    bool   vv[4];
    float  Wsum = 0.f;

    if (s > 0) {
        const int p = s - 1;
        const float ix = g_coords[(size_t)(b*SN + p)*2 + 0];
        const float iy = g_coords[(size_t)(b*SN + p)*2 + 1];
        const float ix0f = floorf(ix), iy0f = floorf(iy);
        const float wx1 = ix - ix0f, wx0 = 1.f - wx1;
        const float wy1 = iy - iy0f, wy0 = 1.f - wy1;
        const int x0 = (int)ix0f, y0 = (int)iy0f;
        const int xs[4] = {x0, x0+1, x0, x0+1};
        const int ys[4] = {y0, y0, y0+1, y0+1};
        const float ws[4] = {wy0*wx0, wy0*wx1, wy1*wx0, wy1*wx1};
        #pragma unroll
        for (int c = 0; c < 4; c++) {
            const int x = xs[c], y = ys[c];
            const bool v2 = (x >= 6) && (x <= 13) && (y >= 6) && (y <= 13);
            vv[c] = v2; w[c] = ws[c];
            tok[c] = b * 64 + (y-6)*8 + (x-6);
            roww[c] = v2 ? (size_t)tok[c] * DIM : 0;
            if (v2) Wsum += ws[c];
        }
    }

    float part;
    float4 sv4;
    if (s == 0) {
        const float4 cq4 = *reinterpret_cast<const float4*>(g_cq + d0);
        part = fmaf(x4.x, cq4.x, fmaf(x4.y, cq4.y, fmaf(x4.z, cq4.z, x4.w * cq4.w)));
        sv4 = make_float4(1.f, 1.f, 1.f, 1.f);
    } else {
        const float4 u4 = *reinterpret_cast<const float4*>(g_u + d0);
        float4 sky = make_float4(Wsum*u4.x, Wsum*u4.y, Wsum*u4.z, Wsum*u4.w);
        sv4 = make_float4(0.f, 0.f, 0.f, 0.f);
        #pragma unroll
        for (int c = 0; c < 4; c++) {
            if (vv[c]) {
                const float4 yv = *reinterpret_cast<const float4*>(g_y + roww[c] + d0);
                const float4 vf = *reinterpret_cast<const float4*>(g_vs + roww[c] + d0);
                sky.x = fmaf(w[c], yv.x, sky.x); sky.y = fmaf(w[c], yv.y, sky.y);
                sky.z = fmaf(w[c], yv.z, sky.z); sky.w = fmaf(w[c], yv.w, sky.w);
                sv4.x = fmaf(w[c], vf.x, sv4.x); sv4.y = fmaf(w[c], vf.y, sv4.y);
                sv4.z = fmaf(w[c], vf.z, sv4.z); sv4.w = fmaf(w[c], vf.w, sv4.w);
            }
        }
        part = fmaf(x4.x, sky.x, fmaf(x4.y, sky.y, fmaf(x4.z, sky.z, x4.w * sky.w)));
    }

    #pragma unroll
    for (int off = 16; off > 0; off >>= 1)
        part += __shfl_xor_sync(0xffffffffu, part, off);
    if (lane == 0) red[wid] = part;
    __syncthreads();
    if (tid == 0) {
        float sum = red[0] + red[1] + red[2] + red[3] + red[4] + red[5];
        if (s == 0) {
            sum += g_sc[1];
        } else {
            float zs = Wsum * g_sc[0];
            #pragma unroll
            for (int c = 0; c < 4; c++)
                if (vv[c]) zs = fmaf(w[c], g_z[tok[c]], zs);
            sum += zs;
        }
        sigsh = 1.f / (1.f + expf(-0.01f * sum));
    }
    __syncthreads();
    const float sg = sigsh;
    float4 o = make_float4(sg * sv4.x, sg * sv4.y, sg * sv4.z, sg * sv4.w);
    *reinterpret_cast<float4*>(out + rbase + d0) = o;
}

// ============================================================
extern "C" void kernel_launch(void* const* d_in, const int* in_sizes, int n_in,
                              void* d_out, int out_size)
{
    const float* x  = (const float*)d_in[0];
    const float* Wq = (const float*)d_in[2];  const float* bq = (const float*)d_in[3];
    const float* Wk = (const float*)d_in[4];  const float* bk = (const float*)d_in[5];
    const float* Wv = (const float*)d_in[6];  const float* bv = (const float*)d_in[7];
    const float* W1 = (const float*)d_in[8];  const float* b1 = (const float*)d_in[9];
    const float* W2 = (const float*)d_in[10]; const float* b2 = (const float*)d_in[11];
    const float* W3 = (const float*)d_in[12]; const float* b3 = (const float*)d_in[13];
    float* out = (float*)d_out;

    // weight folds
    k_weff<<<60, 256>>>(W1, Wq, Wk);
    k_beff<<<1, 64>>>(W1, bq, bk, b1);
    k_gmat<<<144, 256>>>(Wq, Wk);
    k_vec<<<3, 256>>>(Wq, Wk, bq, bk);
    k_scal<<<1, 32>>>(bq, bk);
    // y (G-transform) + V on the 64 reachable tokens/batch
    k_gemm_yv_t<<<128 * 12, 256>>>(x, Wv, bv);
    // per-token scalar z = x.v
    k_z<<<MV / 8, 256>>>(x);
    // fused MLP layer 1 from X
    k_gemm_h1_x<<<392, 256>>>(x);
    // MLP layers 2+3 -> sample, coords
    k_mlp23<<<3136, 256>>>(W2, b2, W3, b3);
    k_coords<<<196, 256>>>();
    // gather + scores + output (no Q anywhere)
    k_epilogue<<<MQK, 192>>>(x, out);
}